// round 7
// baseline (speedup 1.0000x reference)
#include <cuda_runtime.h>
#include <cstdint>

#define T_STEPS 512
#define BATCH   128
#define DIM     512
#define M_ROWS  (T_STEPS * BATCH)   // 65536

typedef unsigned long long u64;

// Scratch
__device__ float g_xproj[(size_t)T_STEPS * BATCH * DIM];       // 134 MB
// h exchange stage: [buf][group][dp 0..255][b 0..7] float2
__device__ float2 g_stage[2][16][256 * 8];                     // 512 KB

// ---------------------------------------------------------------------------
// packed f32x2 helpers (FFMA2 only reachable via PTX)
// ---------------------------------------------------------------------------
__device__ __forceinline__ u64 pack2(float lo, float hi) {
    u64 r;
    asm("mov.b64 %0, {%1, %2};" : "=l"(r) : "f"(lo), "f"(hi));
    return r;
}
__device__ __forceinline__ void unpack2(u64 v, float& lo, float& hi) {
    asm("mov.b64 {%0, %1}, %2;" : "=f"(lo), "=f"(hi) : "l"(v));
}
__device__ __forceinline__ u64 ffma2(u64 a, u64 b, u64 c) {
    u64 d;
    asm("fma.rn.f32x2 %0, %1, %2, %3;" : "=l"(d) : "l"(a), "l"(b), "l"(c));
    return d;
}
__device__ __forceinline__ u64 fadd2(u64 a, u64 b) {
    u64 d;
    asm("add.rn.f32x2 %0, %1, %2;" : "=l"(d) : "l"(a), "l"(b));
    return d;
}

// ============================================================================
// Kernel 1: Xproj = X @ W_in^T. FFMA2 with PRE-DUPLICATED A pairs in SMEM.
// (unchanged from R6 — mechanically sound: 6 LDS.128 + 32 FFMA2 per k)
// ============================================================================
#define GEMM_A_ROW 130   // u64 per k-row (128 + 2 pad)
#define GEMM_B_ROW 132   // floats per k-row
#define GEMM_SMEM  (2*16*GEMM_A_ROW*8 + 2*16*GEMM_B_ROW*4)   // 50176 B

__global__ void __launch_bounds__(256, 2)
xproj_gemm(const float* __restrict__ A, const float* __restrict__ W) {
    extern __shared__ __align__(16) char gsm[];
    u64*   As2 = (u64*)gsm;                                // [2][16][130] dup
    float* Bs  = (float*)(gsm + 2 * 16 * GEMM_A_ROW * 8);  // [2][16][132]

    const int tid = threadIdx.x;
    const int tx = tid & 15;
    const int ty = tid >> 4;
    const int m0 = blockIdx.y * 128;
    const int n0 = blockIdx.x * 128;

    u64 acc2[8][4];
#pragma unroll
    for (int i = 0; i < 8; i++)
#pragma unroll
        for (int j = 0; j < 4; j++) acc2[i][j] = 0ull;

    float4 ra[2], rb[2];

#pragma unroll
    for (int j = 0; j < 2; j++) {
        int i  = tid + j * 256;
        int rr = i >> 2;
        int kk = (i & 3) << 2;
        ra[j] = *(const float4*)(A + (size_t)(m0 + rr) * 512 + kk);
        rb[j] = *(const float4*)(W + (size_t)(n0 + rr) * 512 + kk);
    }
#pragma unroll
    for (int j = 0; j < 2; j++) {
        int i  = tid + j * 256;
        int rr = i >> 2;
        int kk = (i & 3) << 2;
        u64* ad = As2 + (size_t)kk * GEMM_A_ROW + rr;
        ad[0 * GEMM_A_ROW] = pack2(ra[j].x, ra[j].x);
        ad[1 * GEMM_A_ROW] = pack2(ra[j].y, ra[j].y);
        ad[2 * GEMM_A_ROW] = pack2(ra[j].z, ra[j].z);
        ad[3 * GEMM_A_ROW] = pack2(ra[j].w, ra[j].w);
        float* bd = Bs + (size_t)kk * GEMM_B_ROW + rr;
        bd[0 * GEMM_B_ROW] = rb[j].x;
        bd[1 * GEMM_B_ROW] = rb[j].y;
        bd[2 * GEMM_B_ROW] = rb[j].z;
        bd[3 * GEMM_B_ROW] = rb[j].w;
    }
    __syncthreads();

    for (int s = 0; s < 32; s++) {
        const int cb = s & 1;
        if (s < 31) {
            const int kc = (s + 1) * 16;
#pragma unroll
            for (int j = 0; j < 2; j++) {
                int i  = tid + j * 256;
                int rr = i >> 2;
                int kk = (i & 3) << 2;
                ra[j] = *(const float4*)(A + (size_t)(m0 + rr) * 512 + kc + kk);
                rb[j] = *(const float4*)(W + (size_t)(n0 + rr) * 512 + kc + kk);
            }
        }
        const u64*   ab = As2 + (size_t)cb * 16 * GEMM_A_ROW + ty * 8;
        const float* bb = Bs  + (size_t)cb * 16 * GEMM_B_ROW + tx * 8;
#pragma unroll
        for (int k = 0; k < 16; k++) {
            const ulonglong2* ap = (const ulonglong2*)(ab + (size_t)k * GEMM_A_ROW);
            ulonglong2 A01 = ap[0], A23 = ap[1], A45 = ap[2], A67 = ap[3];
            const ulonglong2* bp = (const ulonglong2*)(bb + (size_t)k * GEMM_B_ROW);
            ulonglong2 Bq0 = bp[0], Bq1 = bp[1];
            u64 av[8] = {A01.x, A01.y, A23.x, A23.y, A45.x, A45.y, A67.x, A67.y};
            u64 bv[4] = {Bq0.x, Bq0.y, Bq1.x, Bq1.y};
#pragma unroll
            for (int i = 0; i < 8; i++) {
                acc2[i][0] = ffma2(av[i], bv[0], acc2[i][0]);
                acc2[i][1] = ffma2(av[i], bv[1], acc2[i][1]);
                acc2[i][2] = ffma2(av[i], bv[2], acc2[i][2]);
                acc2[i][3] = ffma2(av[i], bv[3], acc2[i][3]);
            }
        }
        if (s < 31) {
            const int nb = (s + 1) & 1;
#pragma unroll
            for (int j = 0; j < 2; j++) {
                int i  = tid + j * 256;
                int rr = i >> 2;
                int kk = (i & 3) << 2;
                u64* ad = As2 + ((size_t)nb * 16 + kk) * GEMM_A_ROW + rr;
                ad[0 * GEMM_A_ROW] = pack2(ra[j].x, ra[j].x);
                ad[1 * GEMM_A_ROW] = pack2(ra[j].y, ra[j].y);
                ad[2 * GEMM_A_ROW] = pack2(ra[j].z, ra[j].z);
                ad[3 * GEMM_A_ROW] = pack2(ra[j].w, ra[j].w);
                float* bd = Bs + ((size_t)nb * 16 + kk) * GEMM_B_ROW + rr;
                bd[0 * GEMM_B_ROW] = rb[j].x;
                bd[1 * GEMM_B_ROW] = rb[j].y;
                bd[2 * GEMM_B_ROW] = rb[j].z;
                bd[3 * GEMM_B_ROW] = rb[j].w;
            }
        }
        __syncthreads();
    }

#pragma unroll
    for (int i = 0; i < 8; i++) {
        float c0, c1, c2, c3, c4, c5, c6, c7;
        unpack2(acc2[i][0], c0, c1);
        unpack2(acc2[i][1], c2, c3);
        unpack2(acc2[i][2], c4, c5);
        unpack2(acc2[i][3], c6, c7);
        float* cp = g_xproj + (size_t)(m0 + ty * 8 + i) * 512 + n0 + tx * 8;
        *(float4*)cp       = make_float4(c0, c1, c2, c3);
        *(float4*)(cp + 4) = make_float4(c4, c5, c6, c7);
    }
}

// ============================================================================
// Kernel 2: recurrent scan, register-resident W_h.
// 16 clusters x 8 CTAs, 512 threads. Warp w = k-chunk [32w,32w+32);
// lane = d-pair (dims r*64+2*lane, +1). W pairs live in 32 u64 REGISTERS.
// Inner loop: broadcast LDS of hdup[k][b] (pre-duplicated u64), FFMA2 packs
// (d0,d1) -> no movs, no shuffle reduction. Cross-warp reduce via SMEM
// partials; h exchanged via L2 stage + barrier.cluster (release/acquire).
// ============================================================================
// SMEM (u64 units): hdup[2][512][8] = 8192 u64 (64KB); part[16][32][8] = 4096
#define SCAN_SMEM ((8192 + 4096) * 8)    // 98304 B

__global__ void __cluster_dims__(8, 1, 1) __launch_bounds__(512, 1)
rnn_scan(const float* __restrict__ Wh, const float* __restrict__ bh,
         float* __restrict__ out) {
    extern __shared__ __align__(16) u64 smem64[];
    u64* hdup = smem64;            // [2][512 k][8 b] dup u64
    u64* part = smem64 + 8192;     // [16 w][32 dp][8 b] u64

    const int tid  = threadIdx.x;
    const int lane = tid & 31;     // d-pair index 0..31
    const int w    = tid >> 5;     // k-chunk 0..15
    const int r    = blockIdx.x & 7;
    const int g    = blockIdx.x >> 3;

    // ---- load this thread's W pairs into REGISTERS (one-time) ----
    u64 Wreg[32];
    {
        const float* w0p = Wh + (size_t)(r * 64 + 2 * lane) * 512 + w * 32;
        const float* w1p = w0p + 512;
#pragma unroll
        for (int kk = 0; kk < 32; kk++)
            Wreg[kk] = pack2(__ldg(w0p + kk), __ldg(w1p + kk));
    }

    // ---- zero hdup buffer 0 (t=0 reads it) ----
    for (int i = tid; i < 4096; i += 512) hdup[i] = 0ull;
    __syncthreads();

    // ---- reducer role: tid<256 -> (dp=rl, b=rb) ----
    const int rl = tid >> 3;            // dp 0..31 (valid when tid<256)
    const int rb = tid & 7;             // batch-local 0..7
    const int d0 = r * 64 + 2 * rl;     // global dims d0, d0+1
    const int bglob = g * 8 + rb;
    u64 bias2 = 0ull;
    const float* xp_base = g_xproj;
    float2 xp = make_float2(0.f, 0.f);
    if (tid < 256) {
        bias2 = pack2(bh[d0], bh[d0 + 1]);
        xp_base = g_xproj + (size_t)bglob * DIM + d0;
        xp = *(const float2*)xp_base;   // xp(0)
    }

    // dup-fill role (all 512 threads): 4 stage entries, dp=tid>>1, b0=(tid&1)*4
    const int fdp = tid >> 1;
    const int fb0 = (tid & 1) * 4;

    for (int t = 0; t < T_STEPS; t++) {
        const int p = t & 1;

        // ---- compute partials: acc[b] = sum_{k in chunk} W2[k] * h[k][b] ----
        const u64* hbuf = hdup + (size_t)p * 4096 + (size_t)w * 32 * 8;
        u64 acc[8];
#pragma unroll
        for (int i = 0; i < 8; i++) acc[i] = 0ull;
#pragma unroll
        for (int kk = 0; kk < 32; kk++) {
            const ulonglong2* hr = (const ulonglong2*)(hbuf + (size_t)kk * 8);
            ulonglong2 h01 = hr[0], h23 = hr[1], h45 = hr[2], h67 = hr[3];
            acc[0] = ffma2(h01.x, Wreg[kk], acc[0]);
            acc[1] = ffma2(h01.y, Wreg[kk], acc[1]);
            acc[2] = ffma2(h23.x, Wreg[kk], acc[2]);
            acc[3] = ffma2(h23.y, Wreg[kk], acc[3]);
            acc[4] = ffma2(h45.x, Wreg[kk], acc[4]);
            acc[5] = ffma2(h45.y, Wreg[kk], acc[5]);
            acc[6] = ffma2(h67.x, Wreg[kk], acc[6]);
            acc[7] = ffma2(h67.y, Wreg[kk], acc[7]);
        }

        // ---- store partials: part[w][lane][b] ----
        {
            u64* pp = part + (size_t)w * 256 + (size_t)lane * 8;
            ((ulonglong2*)pp)[0] = make_ulonglong2(acc[0], acc[1]);
            ((ulonglong2*)pp)[1] = make_ulonglong2(acc[2], acc[3]);
            ((ulonglong2*)pp)[2] = make_ulonglong2(acc[4], acc[5]);
            ((ulonglong2*)pp)[3] = make_ulonglong2(acc[6], acc[7]);
        }
        __syncthreads();

        // ---- reduce across 16 warps (256 reducer threads) + activation ----
        float h0 = 0.f, h1 = 0.f;
        if (tid < 256) {
            const u64* q = part + (size_t)rl * 8 + rb;
            u64 v[16];
#pragma unroll
            for (int i = 0; i < 16; i++) v[i] = q[(size_t)i * 256];
#pragma unroll
            for (int i = 0; i < 8; i++) v[i] = fadd2(v[i], v[i + 8]);
#pragma unroll
            for (int i = 0; i < 4; i++) v[i] = fadd2(v[i], v[i + 4]);
            v[0] = fadd2(v[0], v[2]);
            v[1] = fadd2(v[1], v[3]);
            v[0] = fadd2(v[0], v[1]);
            u64 z2 = fadd2(fadd2(v[0], pack2(xp.x, xp.y)), bias2);
            float z0, z1;
            unpack2(z2, z0, z1);
            h0 = 1.0f / (1.0f + __expf(-z0));
            h1 = 1.0f / (1.0f + __expf(-z1));
        }

        if (t < T_STEPS - 1) {
            // publish to L2 stage (coalesced 8B per reducer)
            if (tid < 256)
                g_stage[p ^ 1][g][(r * 32 + rl) * 8 + rb] = make_float2(h0, h1);
            asm volatile("barrier.cluster.arrive.aligned;" ::: "memory");
            // prefetch xp(t+1) while peers arrive
            if (tid < 256)
                xp = *(const float2*)(xp_base + (size_t)(t + 1) * BATCH * DIM);
            asm volatile("barrier.cluster.wait.aligned;"   ::: "memory");

            // dup-fill hdup[p^1] from stage (L2, bypass L1 via __ldcg)
            {
                const float4* sg =
                    (const float4*)(g_stage[p ^ 1][g]) + tid * 2;
                float4 q0 = __ldcg(sg);
                float4 q1 = __ldcg(sg + 1);
                u64* hw0 = hdup + (size_t)(p ^ 1) * 4096 + (size_t)(2 * fdp) * 8 + fb0;
                u64* hw1 = hw0 + 8;
                ((ulonglong2*)hw0)[0] = make_ulonglong2(pack2(q0.x, q0.x), pack2(q0.z, q0.z));
                ((ulonglong2*)hw0)[1] = make_ulonglong2(pack2(q1.x, q1.x), pack2(q1.z, q1.z));
                ((ulonglong2*)hw1)[0] = make_ulonglong2(pack2(q0.y, q0.y), pack2(q0.w, q0.w));
                ((ulonglong2*)hw1)[1] = make_ulonglong2(pack2(q1.y, q1.y), pack2(q1.w, q1.w));
            }
            __syncthreads();
        } else if (tid < 256) {
            *(float2*)(out + (size_t)bglob * DIM + d0) = make_float2(h0, h1);
        }
    }
}

// ============================================================================
extern "C" void kernel_launch(void* const* d_in, const int* in_sizes, int n_in,
                              void* d_out, int out_size) {
    const float* X    = (const float*)d_in[0];  // [512,128,512]
    const float* W_in = (const float*)d_in[1];  // [512,512]
    const float* W_h  = (const float*)d_in[2];  // [512,512]
    const float* b_h  = (const float*)d_in[3];  // [512]
    float* out = (float*)d_out;                 // [128,512]

    (void)in_sizes; (void)n_in; (void)out_size;

    cudaFuncSetAttribute(xproj_gemm,
                         cudaFuncAttributeMaxDynamicSharedMemorySize,
                         GEMM_SMEM);
    dim3 g1(DIM / 128, M_ROWS / 128);   // (4, 512)
    xproj_gemm<<<g1, 256, GEMM_SMEM>>>(X, W_in);

    cudaFuncSetAttribute(rnn_scan,
                         cudaFuncAttributeMaxDynamicSharedMemorySize,
                         SCAN_SMEM);
    rnn_scan<<<128, 512, SCAN_SMEM>>>(W_h, b_h, out);
}

// round 8
// speedup vs baseline: 1.3811x; 1.3811x over previous
#include <cuda_runtime.h>
#include <cstdint>

#define T_STEPS 512
#define BATCH   128
#define DIM     512
#define M_ROWS  (T_STEPS * BATCH)   // 65536

typedef unsigned long long u64;

// Scratch
__device__ float g_xproj[(size_t)T_STEPS * BATCH * DIM];  // 134 MB

// ---------------------------------------------------------------------------
// packed f32x2 helpers (FFMA2/FMUL2 only reachable via PTX)
// ---------------------------------------------------------------------------
__device__ __forceinline__ u64 pack2(float lo, float hi) {
    u64 r;
    asm("mov.b64 %0, {%1, %2};" : "=l"(r) : "f"(lo), "f"(hi));
    return r;
}
__device__ __forceinline__ void unpack2(u64 v, float& lo, float& hi) {
    asm("mov.b64 {%0, %1}, %2;" : "=f"(lo), "=f"(hi) : "l"(v));
}
__device__ __forceinline__ u64 ffma2(u64 a, u64 b, u64 c) {
    u64 d;
    asm("fma.rn.f32x2 %0, %1, %2, %3;" : "=l"(d) : "l"(a), "l"(b), "l"(c));
    return d;
}
__device__ __forceinline__ u64 fmul2(u64 a, u64 b) {
    u64 d;
    asm("mul.rn.f32x2 %0, %1, %2;" : "=l"(d) : "l"(a), "l"(b));
    return d;
}
__device__ __forceinline__ u64 fadd2(u64 a, u64 b) {
    u64 d;
    asm("add.rn.f32x2 %0, %1, %2;" : "=l"(d) : "l"(a), "l"(b));
    return d;
}

// ============================================================================
// Kernel 1: Xproj = X @ W_in^T. FFMA2 with PRE-DUPLICATED A pairs in SMEM.
// 128x128 tile, BK=16, 256 threads, 8x8 micro, acc packed over n-pairs.
// ============================================================================
#define GEMM_A_ROW 130   // u64 per k-row (128 + 2 pad)
#define GEMM_B_ROW 132   // floats per k-row
#define GEMM_SMEM  (2*16*GEMM_A_ROW*8 + 2*16*GEMM_B_ROW*4)   // 50176 B

__global__ void __launch_bounds__(256, 2)
xproj_gemm(const float* __restrict__ A, const float* __restrict__ W) {
    extern __shared__ __align__(16) char gsm[];
    u64*   As2 = (u64*)gsm;                                // [2][16][130] dup
    float* Bs  = (float*)(gsm + 2 * 16 * GEMM_A_ROW * 8);  // [2][16][132]

    const int tid = threadIdx.x;
    const int tx = tid & 15;
    const int ty = tid >> 4;
    const int m0 = blockIdx.y * 128;
    const int n0 = blockIdx.x * 128;

    u64 acc2[8][4];
#pragma unroll
    for (int i = 0; i < 8; i++)
#pragma unroll
        for (int j = 0; j < 4; j++) acc2[i][j] = 0ull;

    float4 ra[2], rb[2];

#pragma unroll
    for (int j = 0; j < 2; j++) {
        int i  = tid + j * 256;
        int rr = i >> 2;
        int kk = (i & 3) << 2;
        ra[j] = *(const float4*)(A + (size_t)(m0 + rr) * 512 + kk);
        rb[j] = *(const float4*)(W + (size_t)(n0 + rr) * 512 + kk);
    }
#pragma unroll
    for (int j = 0; j < 2; j++) {
        int i  = tid + j * 256;
        int rr = i >> 2;
        int kk = (i & 3) << 2;
        u64* ad = As2 + (size_t)kk * GEMM_A_ROW + rr;
        ad[0 * GEMM_A_ROW] = pack2(ra[j].x, ra[j].x);
        ad[1 * GEMM_A_ROW] = pack2(ra[j].y, ra[j].y);
        ad[2 * GEMM_A_ROW] = pack2(ra[j].z, ra[j].z);
        ad[3 * GEMM_A_ROW] = pack2(ra[j].w, ra[j].w);
        float* bd = Bs + (size_t)kk * GEMM_B_ROW + rr;
        bd[0 * GEMM_B_ROW] = rb[j].x;
        bd[1 * GEMM_B_ROW] = rb[j].y;
        bd[2 * GEMM_B_ROW] = rb[j].z;
        bd[3 * GEMM_B_ROW] = rb[j].w;
    }
    __syncthreads();

    for (int s = 0; s < 32; s++) {
        const int cb = s & 1;
        if (s < 31) {
            const int kc = (s + 1) * 16;
#pragma unroll
            for (int j = 0; j < 2; j++) {
                int i  = tid + j * 256;
                int rr = i >> 2;
                int kk = (i & 3) << 2;
                ra[j] = *(const float4*)(A + (size_t)(m0 + rr) * 512 + kc + kk);
                rb[j] = *(const float4*)(W + (size_t)(n0 + rr) * 512 + kc + kk);
            }
        }
        const u64*   ab = As2 + (size_t)cb * 16 * GEMM_A_ROW + ty * 8;
        const float* bb = Bs  + (size_t)cb * 16 * GEMM_B_ROW + tx * 8;
#pragma unroll
        for (int k = 0; k < 16; k++) {
            const ulonglong2* ap = (const ulonglong2*)(ab + (size_t)k * GEMM_A_ROW);
            ulonglong2 A01 = ap[0], A23 = ap[1], A45 = ap[2], A67 = ap[3];
            const ulonglong2* bp = (const ulonglong2*)(bb + (size_t)k * GEMM_B_ROW);
            ulonglong2 Bq0 = bp[0], Bq1 = bp[1];
            u64 av[8] = {A01.x, A01.y, A23.x, A23.y, A45.x, A45.y, A67.x, A67.y};
            u64 bv[4] = {Bq0.x, Bq0.y, Bq1.x, Bq1.y};
#pragma unroll
            for (int i = 0; i < 8; i++) {
                acc2[i][0] = ffma2(av[i], bv[0], acc2[i][0]);
                acc2[i][1] = ffma2(av[i], bv[1], acc2[i][1]);
                acc2[i][2] = ffma2(av[i], bv[2], acc2[i][2]);
                acc2[i][3] = ffma2(av[i], bv[3], acc2[i][3]);
            }
        }
        if (s < 31) {
            const int nb = (s + 1) & 1;
#pragma unroll
            for (int j = 0; j < 2; j++) {
                int i  = tid + j * 256;
                int rr = i >> 2;
                int kk = (i & 3) << 2;
                u64* ad = As2 + ((size_t)nb * 16 + kk) * GEMM_A_ROW + rr;
                ad[0 * GEMM_A_ROW] = pack2(ra[j].x, ra[j].x);
                ad[1 * GEMM_A_ROW] = pack2(ra[j].y, ra[j].y);
                ad[2 * GEMM_A_ROW] = pack2(ra[j].z, ra[j].z);
                ad[3 * GEMM_A_ROW] = pack2(ra[j].w, ra[j].w);
                float* bd = Bs + ((size_t)nb * 16 + kk) * GEMM_B_ROW + rr;
                bd[0 * GEMM_B_ROW] = rb[j].x;
                bd[1 * GEMM_B_ROW] = rb[j].y;
                bd[2 * GEMM_B_ROW] = rb[j].z;
                bd[3 * GEMM_B_ROW] = rb[j].w;
            }
        }
        __syncthreads();
    }

#pragma unroll
    for (int i = 0; i < 8; i++) {
        float c0, c1, c2, c3, c4, c5, c6, c7;
        unpack2(acc2[i][0], c0, c1);
        unpack2(acc2[i][1], c2, c3);
        unpack2(acc2[i][2], c4, c5);
        unpack2(acc2[i][3], c6, c7);
        float* cp = g_xproj + (size_t)(m0 + ty * 8 + i) * 512 + n0 + tx * 8;
        *(float4*)cp       = make_float4(c0, c1, c2, c3);
        *(float4*)(cp + 4) = make_float4(c4, c5, c6, c7);
    }
}

// ============================================================================
// Kernel 2: recurrent scan — R3 skeleton (8 warps, 256 thr) with a
// SOFTWARE-PIPELINED inner loop (loads for ki+1 issued before compute of ki)
// and xp prefetch between barrier arrive/wait. DSMEM push exchange as R3.
// ============================================================================
#define HB_BUF_BYTES 16384           // 8 batch x 512 dims x 4B
#define WT2_FLOATS   (64 * 512)      // 128 KB
#define SCAN_SMEM    ((WT2_FLOATS + 2 * 8 * 512) * 4)   // 163840 B

#define RED2(OFF)                                                             \
    {                                                                         \
        const bool hi_ = (lane & (OFF)) != 0;                                 \
        _Pragma("unroll")                                                     \
        for (int i_ = 0; i_ < (OFF); i_++) {                                  \
            u64 send_ = hi_ ? acc2[i_] : acc2[i_ + (OFF)];                    \
            float sl_, sh_;                                                   \
            unpack2(send_, sl_, sh_);                                         \
            sl_ = __shfl_xor_sync(0xffffffffu, sl_, (OFF));                   \
            sh_ = __shfl_xor_sync(0xffffffffu, sh_, (OFF));                   \
            u64 keep_ = hi_ ? acc2[i_ + (OFF)] : acc2[i_];                    \
            acc2[i_] = fadd2(keep_, pack2(sl_, sh_));                         \
        }                                                                     \
    }

__global__ void __cluster_dims__(8, 1, 1) __launch_bounds__(256, 1)
rnn_scan(const float* __restrict__ Wh, const float* __restrict__ bh,
         float* __restrict__ out) {
    extern __shared__ __align__(16) float smem[];
    float* Wt = smem;                    // d-pair interleaved W_h slice
    float* hb = smem + WT2_FLOATS;       // [2][8][512] double-buffered h

    const int tid  = threadIdx.x;
    const int lane = tid & 31;
    const int wid  = tid >> 5;           // warp -> dims [wid*8, wid*8+8)
    const int r    = blockIdx.x & 7;     // cluster rank -> dim slice
    const int g    = blockIdx.x >> 3;    // batch group

    // load W_h slice, interleaved by d-pairs:
    // Wt[p*1024 + 2k + parity] = W_h[r*64 + 2p + parity][k]
    for (int idx = tid; idx < 64 * 512 / 4; idx += 256) {
        int dl = idx >> 7;               // local dim 0..63
        int k4 = (idx & 127) << 2;       // k, step 4
        float4 v = __ldg((const float4*)(Wh + (size_t)(r * 64 + dl) * 512 + k4));
        float* wdst = Wt + (dl >> 1) * 1024 + (dl & 1);
        wdst[2 * (k4 + 0)] = v.x;
        wdst[2 * (k4 + 1)] = v.y;
        wdst[2 * (k4 + 2)] = v.z;
        wdst[2 * (k4 + 3)] = v.w;
    }
    // zero ONLY buffer 0 (buffer 1 is written remotely at t=0)
    {
        float4  z4  = make_float4(0.f, 0.f, 0.f, 0.f);
        float4* hd4 = (float4*)hb;
        for (int i = tid; i < 8 * 512 / 4; i += 256) hd4[i] = z4;
    }
    __syncthreads();

    // lane j -> outputs (b = j>>2, d = wid*8 + (j&3)*2 .. +1)
    const int bl    = lane >> 2;
    const int dl2   = (lane & 3) * 2;
    const int dglob = r * 64 + wid * 8 + dl2;
    const int bglob = g * 8 + bl;

    const u64 bias2 = pack2(bh[dglob], bh[dglob + 1]);
    const float* xp_ptr = g_xproj + (size_t)bglob * DIM + dglob;

    // DSMEM destinations: this thread's float2 slot in every rank's hb
    uint32_t hb_u32;
    {
        size_t gp = __cvta_generic_to_shared(hb);
        hb_u32 = (uint32_t)gp;
    }
    const uint32_t slot_off = (uint32_t)(bl * 2048 + dglob * 4);
    uint32_t dst[8];
#pragma unroll
    for (int rr = 0; rr < 8; rr++) {
        asm("mapa.shared::cluster.u32 %0, %1, %2;"
            : "=r"(dst[rr]) : "r"(hb_u32 + slot_off), "r"(rr));
    }

    const float* WtW = Wt + (size_t)(wid * 4) * 1024;   // warp's 4 d-pair rows
    const int kbase = lane * 2;

    float2 xp = *(const float2*)xp_ptr;              // xp(0)

    for (int t = 0; t < T_STEPS; t++) {
        const int p = t & 1;
        const float* hbp = hb + p * 4096;            // read buffer

        u64 acc2[32];

        // ---- software-pipelined inner loop: load ki+1 while computing ki ---
        ulonglong2 wqA[4], wqB[4];
        float2     hvA[8], hvB[8];
        {
            const int k = kbase;                     // ki = 0
#pragma unroll
            for (int dd = 0; dd < 4; dd++)
                wqA[dd] = *(const ulonglong2*)(WtW + dd * 1024 + 2 * k);
#pragma unroll
            for (int b = 0; b < 8; b++)
                hvA[b] = *(const float2*)(hbp + b * 512 + k);
        }
#pragma unroll
        for (int ki = 0; ki < 8; ki++) {
            const ulonglong2* wq = (ki & 1) ? wqB : wqA;
            const float2*     hv = (ki & 1) ? hvB : hvA;
            ulonglong2* wqn = (ki & 1) ? wqA : wqB;
            float2*     hvn = (ki & 1) ? hvA : hvB;
            if (ki < 7) {
                const int kn = (ki + 1) * 64 + kbase;
#pragma unroll
                for (int dd = 0; dd < 4; dd++)
                    wqn[dd] = *(const ulonglong2*)(WtW + dd * 1024 + 2 * kn);
#pragma unroll
                for (int b = 0; b < 8; b++)
                    hvn[b] = *(const float2*)(hbp + b * 512 + kn);
            }
            if (ki == 0) {
#pragma unroll
                for (int b = 0; b < 8; b++) {
                    u64 hd0 = pack2(hv[b].x, hv[b].x);
                    u64 hd1 = pack2(hv[b].y, hv[b].y);
#pragma unroll
                    for (int dd = 0; dd < 4; dd++) {
                        acc2[b * 4 + dd] = fmul2(hd0, wq[dd].x);
                        acc2[b * 4 + dd] = ffma2(hd1, wq[dd].y, acc2[b * 4 + dd]);
                    }
                }
            } else {
#pragma unroll
                for (int b = 0; b < 8; b++) {
                    u64 hd0 = pack2(hv[b].x, hv[b].x);
                    u64 hd1 = pack2(hv[b].y, hv[b].y);
#pragma unroll
                    for (int dd = 0; dd < 4; dd++) {
                        acc2[b * 4 + dd] = ffma2(hd0, wq[dd].x, acc2[b * 4 + dd]);
                        acc2[b * 4 + dd] = ffma2(hd1, wq[dd].y, acc2[b * 4 + dd]);
                    }
                }
            }
        }

        // butterfly: 32 packed pairs over 32 lanes -> lane holds item `lane`
        RED2(16) RED2(8) RED2(4) RED2(2) RED2(1)

        u64 z2 = fadd2(fadd2(acc2[0], pack2(xp.x, xp.y)), bias2);
        float z0, z1;
        unpack2(z2, z0, z1);
        const float h0 = 1.0f / (1.0f + __expf(-z0));
        const float h1 = 1.0f / (1.0f + __expf(-z1));
        const u64 hh = pack2(h0, h1);

        if (t < T_STEPS - 1) {
            // push this float2 into every rank's write buffer via DSMEM
            const uint32_t boff = (uint32_t)((p ^ 1) * HB_BUF_BYTES);
#pragma unroll
            for (int rr = 0; rr < 8; rr++) {
                asm volatile("st.shared::cluster.u64 [%0], %1;"
                             :: "r"(dst[rr] + boff), "l"(hh) : "memory");
            }
            asm volatile("barrier.cluster.arrive.aligned;" ::: "memory");
            // prefetch xp(t+1) while peers finish pushing/arriving
            xp = __ldg((const float2*)(xp_ptr + (size_t)(t + 1) * BATCH * DIM));
            asm volatile("barrier.cluster.wait.aligned;"   ::: "memory");
        } else {
            *(float2*)(out + (size_t)bglob * DIM + dglob) = make_float2(h0, h1);
        }
    }
}

// ============================================================================
extern "C" void kernel_launch(void* const* d_in, const int* in_sizes, int n_in,
                              void* d_out, int out_size) {
    const float* X    = (const float*)d_in[0];  // [512,128,512]
    const float* W_in = (const float*)d_in[1];  // [512,512]
    const float* W_h  = (const float*)d_in[2];  // [512,512]
    const float* b_h  = (const float*)d_in[3];  // [512]
    float* out = (float*)d_out;                 // [128,512]

    (void)in_sizes; (void)n_in; (void)out_size;

    cudaFuncSetAttribute(xproj_gemm,
                         cudaFuncAttributeMaxDynamicSharedMemorySize,
                         GEMM_SMEM);
    dim3 g1(DIM / 128, M_ROWS / 128);   // (4, 512)
    xproj_gemm<<<g1, 256, GEMM_SMEM>>>(X, W_in);

    cudaFuncSetAttribute(rnn_scan,
                         cudaFuncAttributeMaxDynamicSharedMemorySize,
                         SCAN_SMEM);
    rnn_scan<<<128, 256, SCAN_SMEM>>>(W_h, b_h, out);
}

// round 9
// speedup vs baseline: 1.4622x; 1.0587x over previous
#include <cuda_runtime.h>
#include <cstdint>

#define T_STEPS 512
#define BATCH   128
#define DIM     512
#define M_ROWS  (T_STEPS * BATCH)   // 65536

typedef unsigned long long u64;

// Scratch
__device__ float g_xproj[(size_t)T_STEPS * BATCH * DIM];  // 134 MB

// ---------------------------------------------------------------------------
// packed f32x2 helpers (FFMA2 only reachable via PTX)
// ---------------------------------------------------------------------------
__device__ __forceinline__ u64 pack2(float lo, float hi) {
    u64 r;
    asm("mov.b64 %0, {%1, %2};" : "=l"(r) : "f"(lo), "f"(hi));
    return r;
}
__device__ __forceinline__ void unpack2(u64 v, float& lo, float& hi) {
    asm("mov.b64 {%0, %1}, %2;" : "=f"(lo), "=f"(hi) : "l"(v));
}
__device__ __forceinline__ u64 ffma2(u64 a, u64 b, u64 c) {
    u64 d;
    asm("fma.rn.f32x2 %0, %1, %2, %3;" : "=l"(d) : "l"(a), "l"(b), "l"(c));
    return d;
}
__device__ __forceinline__ u64 fadd2(u64 a, u64 b) {
    u64 d;
    asm("add.rn.f32x2 %0, %1, %2;" : "=l"(d) : "l"(a), "l"(b));
    return d;
}

// mbarrier helpers
__device__ __forceinline__ void mbar_init(uint32_t mb, uint32_t cnt) {
    asm volatile("mbarrier.init.shared.b64 [%0], %1;" :: "r"(mb), "r"(cnt)
                 : "memory");
}
__device__ __forceinline__ void mbar_expect_tx(uint32_t mb, uint32_t bytes) {
    asm volatile("mbarrier.arrive.expect_tx.shared.b64 _, [%0], %1;"
                 :: "r"(mb), "r"(bytes) : "memory");
}
__device__ __forceinline__ void mbar_wait_parity(uint32_t mb, uint32_t par) {
    uint32_t done;
    asm volatile(
        "{\n\t.reg .pred p;\n\t"
        "mbarrier.try_wait.parity.acquire.cta.shared::cta.b64 p, [%1], %2;\n\t"
        "selp.b32 %0, 1, 0, p;\n\t}"
        : "=r"(done) : "r"(mb), "r"(par) : "memory");
    if (!done) {
        asm volatile(
            "{\n\t.reg .pred P1;\n\t"
            "WAIT_LOOP_%=:\n\t"
            "mbarrier.try_wait.parity.acquire.cta.shared::cta.b64 P1, [%0], %1, 0x989680;\n\t"
            "@P1 bra.uni WAIT_DONE_%=;\n\t"
            "bra.uni WAIT_LOOP_%=;\n\t"
            "WAIT_DONE_%=:\n\t}"
            :: "r"(mb), "r"(par) : "memory");
    }
}
__device__ __forceinline__ void st_async_cluster_u64(uint32_t dst, u64 val,
                                                     uint32_t rmb) {
    asm volatile(
        "st.async.shared::cluster.mbarrier::complete_tx::bytes.b64 [%0], %1, [%2];"
        :: "r"(dst), "l"(val), "r"(rmb) : "memory");
}

// ============================================================================
// Kernel 1: Xproj = X @ W_in^T. FFMA2 with PRE-DUPLICATED A pairs in SMEM.
// (unchanged — ~0.76 ms, near the FFMA2 floor)
// ============================================================================
#define GEMM_A_ROW 130   // u64 per k-row (128 + 2 pad)
#define GEMM_B_ROW 132   // floats per k-row
#define GEMM_SMEM  (2*16*GEMM_A_ROW*8 + 2*16*GEMM_B_ROW*4)   // 50176 B

__global__ void __launch_bounds__(256, 2)
xproj_gemm(const float* __restrict__ A, const float* __restrict__ W) {
    extern __shared__ __align__(16) char gsm[];
    u64*   As2 = (u64*)gsm;                                // [2][16][130] dup
    float* Bs  = (float*)(gsm + 2 * 16 * GEMM_A_ROW * 8);  // [2][16][132]

    const int tid = threadIdx.x;
    const int tx = tid & 15;
    const int ty = tid >> 4;
    const int m0 = blockIdx.y * 128;
    const int n0 = blockIdx.x * 128;

    u64 acc2[8][4];
#pragma unroll
    for (int i = 0; i < 8; i++)
#pragma unroll
        for (int j = 0; j < 4; j++) acc2[i][j] = 0ull;

    float4 ra[2], rb[2];

#pragma unroll
    for (int j = 0; j < 2; j++) {
        int i  = tid + j * 256;
        int rr = i >> 2;
        int kk = (i & 3) << 2;
        ra[j] = *(const float4*)(A + (size_t)(m0 + rr) * 512 + kk);
        rb[j] = *(const float4*)(W + (size_t)(n0 + rr) * 512 + kk);
    }
#pragma unroll
    for (int j = 0; j < 2; j++) {
        int i  = tid + j * 256;
        int rr = i >> 2;
        int kk = (i & 3) << 2;
        u64* ad = As2 + (size_t)kk * GEMM_A_ROW + rr;
        ad[0 * GEMM_A_ROW] = pack2(ra[j].x, ra[j].x);
        ad[1 * GEMM_A_ROW] = pack2(ra[j].y, ra[j].y);
        ad[2 * GEMM_A_ROW] = pack2(ra[j].z, ra[j].z);
        ad[3 * GEMM_A_ROW] = pack2(ra[j].w, ra[j].w);
        float* bd = Bs + (size_t)kk * GEMM_B_ROW + rr;
        bd[0 * GEMM_B_ROW] = rb[j].x;
        bd[1 * GEMM_B_ROW] = rb[j].y;
        bd[2 * GEMM_B_ROW] = rb[j].z;
        bd[3 * GEMM_B_ROW] = rb[j].w;
    }
    __syncthreads();

    for (int s = 0; s < 32; s++) {
        const int cb = s & 1;
        if (s < 31) {
            const int kc = (s + 1) * 16;
#pragma unroll
            for (int j = 0; j < 2; j++) {
                int i  = tid + j * 256;
                int rr = i >> 2;
                int kk = (i & 3) << 2;
                ra[j] = *(const float4*)(A + (size_t)(m0 + rr) * 512 + kc + kk);
                rb[j] = *(const float4*)(W + (size_t)(n0 + rr) * 512 + kc + kk);
            }
        }
        const u64*   ab = As2 + (size_t)cb * 16 * GEMM_A_ROW + ty * 8;
        const float* bb = Bs  + (size_t)cb * 16 * GEMM_B_ROW + tx * 8;
#pragma unroll
        for (int k = 0; k < 16; k++) {
            const ulonglong2* ap = (const ulonglong2*)(ab + (size_t)k * GEMM_A_ROW);
            ulonglong2 A01 = ap[0], A23 = ap[1], A45 = ap[2], A67 = ap[3];
            const ulonglong2* bp = (const ulonglong2*)(bb + (size_t)k * GEMM_B_ROW);
            ulonglong2 Bq0 = bp[0], Bq1 = bp[1];
            u64 av[8] = {A01.x, A01.y, A23.x, A23.y, A45.x, A45.y, A67.x, A67.y};
            u64 bv[4] = {Bq0.x, Bq0.y, Bq1.x, Bq1.y};
#pragma unroll
            for (int i = 0; i < 8; i++) {
                acc2[i][0] = ffma2(av[i], bv[0], acc2[i][0]);
                acc2[i][1] = ffma2(av[i], bv[1], acc2[i][1]);
                acc2[i][2] = ffma2(av[i], bv[2], acc2[i][2]);
                acc2[i][3] = ffma2(av[i], bv[3], acc2[i][3]);
            }
        }
        if (s < 31) {
            const int nb = (s + 1) & 1;
#pragma unroll
            for (int j = 0; j < 2; j++) {
                int i  = tid + j * 256;
                int rr = i >> 2;
                int kk = (i & 3) << 2;
                u64* ad = As2 + ((size_t)nb * 16 + kk) * GEMM_A_ROW + rr;
                ad[0 * GEMM_A_ROW] = pack2(ra[j].x, ra[j].x);
                ad[1 * GEMM_A_ROW] = pack2(ra[j].y, ra[j].y);
                ad[2 * GEMM_A_ROW] = pack2(ra[j].z, ra[j].z);
                ad[3 * GEMM_A_ROW] = pack2(ra[j].w, ra[j].w);
                float* bd = Bs + ((size_t)nb * 16 + kk) * GEMM_B_ROW + rr;
                bd[0 * GEMM_B_ROW] = rb[j].x;
                bd[1 * GEMM_B_ROW] = rb[j].y;
                bd[2 * GEMM_B_ROW] = rb[j].z;
                bd[3 * GEMM_B_ROW] = rb[j].w;
            }
        }
        __syncthreads();
    }

#pragma unroll
    for (int i = 0; i < 8; i++) {
        float c0, c1, c2, c3, c4, c5, c6, c7;
        unpack2(acc2[i][0], c0, c1);
        unpack2(acc2[i][1], c2, c3);
        unpack2(acc2[i][2], c4, c5);
        unpack2(acc2[i][3], c6, c7);
        float* cp = g_xproj + (size_t)(m0 + ty * 8 + i) * 512 + n0 + tx * 8;
        *(float4*)cp       = make_float4(c0, c1, c2, c3);
        *(float4*)(cp + 4) = make_float4(c4, c5, c6, c7);
    }
}

// ============================================================================
// Kernel 2: recurrent scan — R3 structure (8 warps), but the per-step
// barrier.cluster is replaced by st.async + mbarrier complete_tx accounting:
// each CTA's mbar[q] expects 16384 tx-bytes (2048 threads x 8B) per phase;
// waiters wake on data arrival instead of a global barrier handshake.
// ============================================================================
#define HB_BUF_BYTES 16384           // 8 batch x 512 dims x 4B
#define WT2_FLOATS   (64 * 512)      // 128 KB
#define MBAR_OFF     ((WT2_FLOATS + 2 * 8 * 512) * 4)   // 163840
#define SCAN_SMEM    (MBAR_OFF + 16)                     // + 2 mbarriers
#define TX_BYTES     16384u          // 2048 threads x 8B into each CTA

#define RED2(OFF)                                                             \
    {                                                                         \
        const bool hi_ = (lane & (OFF)) != 0;                                 \
        _Pragma("unroll")                                                     \
        for (int i_ = 0; i_ < (OFF); i_++) {                                  \
            u64 send_ = hi_ ? acc2[i_] : acc2[i_ + (OFF)];                    \
            float sl_, sh_;                                                   \
            unpack2(send_, sl_, sh_);                                         \
            sl_ = __shfl_xor_sync(0xffffffffu, sl_, (OFF));                   \
            sh_ = __shfl_xor_sync(0xffffffffu, sh_, (OFF));                   \
            u64 keep_ = hi_ ? acc2[i_ + (OFF)] : acc2[i_];                    \
            acc2[i_] = fadd2(keep_, pack2(sl_, sh_));                         \
        }                                                                     \
    }

__global__ void __cluster_dims__(8, 1, 1) __launch_bounds__(256, 1)
rnn_scan(const float* __restrict__ Wh, const float* __restrict__ bh,
         float* __restrict__ out) {
    extern __shared__ __align__(16) float smem[];
    float* Wt = smem;                    // d-pair interleaved W_h slice
    float* hb = smem + WT2_FLOATS;       // [2][8][512] double-buffered h

    const int tid  = threadIdx.x;
    const int lane = tid & 31;
    const int wid  = tid >> 5;           // warp -> dims [wid*8, wid*8+8)
    const int r    = blockIdx.x & 7;     // cluster rank -> dim slice
    const int g    = blockIdx.x >> 3;    // batch group

    const uint32_t smem_u32 = (uint32_t)__cvta_generic_to_shared(smem);
    const uint32_t mb_u32   = smem_u32 + MBAR_OFF;   // mbar[0], mbar[1]

    // load W_h slice, interleaved by d-pairs:
    // Wt[p*1024 + 2k + parity] = W_h[r*64 + 2p + parity][k]
    for (int idx = tid; idx < 64 * 512 / 4; idx += 256) {
        int dl = idx >> 7;               // local dim 0..63
        int k4 = (idx & 127) << 2;       // k, step 4
        float4 v = __ldg((const float4*)(Wh + (size_t)(r * 64 + dl) * 512 + k4));
        float* wdst = Wt + (dl >> 1) * 1024 + (dl & 1);
        wdst[2 * (k4 + 0)] = v.x;
        wdst[2 * (k4 + 1)] = v.y;
        wdst[2 * (k4 + 2)] = v.z;
        wdst[2 * (k4 + 3)] = v.w;
    }
    // zero ONLY buffer 0 (buffer 1 is written remotely at t=0)
    {
        float4  z4  = make_float4(0.f, 0.f, 0.f, 0.f);
        float4* hd4 = (float4*)hb;
        for (int i = tid; i < 8 * 512 / 4; i += 256) hd4[i] = z4;
    }
    if (tid == 0) {
        mbar_init(mb_u32 + 0, 1);
        mbar_init(mb_u32 + 8, 1);
    }
    __syncthreads();
    // all mbarriers valid cluster-wide before any expect/store
    asm volatile("barrier.cluster.arrive.aligned;" ::: "memory");
    asm volatile("barrier.cluster.wait.aligned;"   ::: "memory");
    if (tid == 0) {
        mbar_expect_tx(mb_u32 + 0, TX_BYTES);   // phase 0: step-1 stores
        mbar_expect_tx(mb_u32 + 8, TX_BYTES);   // phase 0: step-0 stores
    }
    // expects posted before any peer can store
    asm volatile("barrier.cluster.arrive.aligned;" ::: "memory");
    asm volatile("barrier.cluster.wait.aligned;"   ::: "memory");

    // lane j -> outputs (b = j>>2, d = wid*8 + (j&3)*2 .. +1)
    const int bl    = lane >> 2;
    const int dl2   = (lane & 3) * 2;
    const int dglob = r * 64 + wid * 8 + dl2;
    const int bglob = g * 8 + bl;

    const u64 bias2 = pack2(bh[dglob], bh[dglob + 1]);
    const float* xp_ptr = g_xproj + (size_t)bglob * DIM + dglob;

    // DSMEM destinations: this thread's float2 slot + mbar in every rank
    const uint32_t hb_u32 = smem_u32 + WT2_FLOATS * 4;
    const uint32_t slot_off = (uint32_t)(bl * 2048 + dglob * 4);
    uint32_t dst[8], rmb[8];
#pragma unroll
    for (int rr = 0; rr < 8; rr++) {
        asm("mapa.shared::cluster.u32 %0, %1, %2;"
            : "=r"(dst[rr]) : "r"(hb_u32 + slot_off), "r"(rr));
        asm("mapa.shared::cluster.u32 %0, %1, %2;"
            : "=r"(rmb[rr]) : "r"(mb_u32), "r"(rr));
    }

    const float* WtW = Wt + (size_t)(wid * 4) * 1024;   // warp's 4 d-pair rows

    float2 xp = *(const float2*)xp_ptr;              // xp(0)
    uint32_t ph0 = 0, ph1 = 0;

    for (int t = 0; t < T_STEPS; t++) {
        const int p = t & 1;
        const float* hbp = hb + p * 4096;            // read buffer

        if (t > 0) {
            // wait for all step-(t-1) stores into hb[p]
            const uint32_t mb = mb_u32 + (uint32_t)p * 8;
            mbar_wait_parity(mb, p ? ph1 : ph0);
            if (p) ph1 ^= 1; else ph0 ^= 1;
            // repost expectation for this mbar's NEXT phase (step t+1 stores);
            // safe: any peer's step-(t+1) store causally follows our step-t
            // stores, which are issued after this point.
            if (tid == 0) mbar_expect_tx(mb, TX_BYTES);
        }

        u64 acc2[32];
#pragma unroll
        for (int i = 0; i < 32; i++) acc2[i] = 0ull;

        // lane covers k = ki*64 + lane*2 (+1)
#pragma unroll 2
        for (int ki = 0; ki < 8; ki++) {
            const int k = ki * 64 + lane * 2;
            ulonglong2 wq[4];
#pragma unroll
            for (int dd = 0; dd < 4; dd++)
                wq[dd] = *(const ulonglong2*)(WtW + dd * 1024 + 2 * k);
#pragma unroll
            for (int b = 0; b < 8; b++) {
                float2 hv = *(const float2*)(hbp + b * 512 + k);
                u64 hd0 = pack2(hv.x, hv.x);
                u64 hd1 = pack2(hv.y, hv.y);
#pragma unroll
                for (int dd = 0; dd < 4; dd++) {
                    acc2[b * 4 + dd] = ffma2(hd0, wq[dd].x, acc2[b * 4 + dd]);
                    acc2[b * 4 + dd] = ffma2(hd1, wq[dd].y, acc2[b * 4 + dd]);
                }
            }
        }

        // butterfly: 32 packed pairs over 32 lanes -> lane holds item `lane`
        RED2(16) RED2(8) RED2(4) RED2(2) RED2(1)

        u64 z2 = fadd2(fadd2(acc2[0], pack2(xp.x, xp.y)), bias2);
        float z0, z1;
        unpack2(z2, z0, z1);
        const float h0 = 1.0f / (1.0f + __expf(-z0));
        const float h1 = 1.0f / (1.0f + __expf(-z1));
        const u64 hh = pack2(h0, h1);

        if (t < T_STEPS - 1) {
            const int q = p ^ 1;
            const uint32_t boff = (uint32_t)(q * HB_BUF_BYTES);
            const uint32_t moff = (uint32_t)(q * 8);
            // async push + per-store tx accounting on the destination mbar
#pragma unroll
            for (int rr = 0; rr < 8; rr++)
                st_async_cluster_u64(dst[rr] + boff, hh, rmb[rr] + moff);
            // prefetch xp(t+1) while stores drain
            xp = __ldg((const float2*)(xp_ptr + (size_t)(t + 1) * BATCH * DIM));
        } else {
            *(float2*)(out + (size_t)bglob * DIM + dglob) = make_float2(h0, h1);
        }
    }

    // keep the cluster alive until everyone is done (in-flight async stores)
    asm volatile("barrier.cluster.arrive.aligned;" ::: "memory");
    asm volatile("barrier.cluster.wait.aligned;"   ::: "memory");
}

// ============================================================================
extern "C" void kernel_launch(void* const* d_in, const int* in_sizes, int n_in,
                              void* d_out, int out_size) {
    const float* X    = (const float*)d_in[0];  // [512,128,512]
    const float* W_in = (const float*)d_in[1];  // [512,512]
    const float* W_h  = (const float*)d_in[2];  // [512,512]
    const float* b_h  = (const float*)d_in[3];  // [512]
    float* out = (float*)d_out;                 // [128,512]

    (void)in_sizes; (void)n_in; (void)out_size;

    cudaFuncSetAttribute(xproj_gemm,
                         cudaFuncAttributeMaxDynamicSharedMemorySize,
                         GEMM_SMEM);
    dim3 g1(DIM / 128, M_ROWS / 128);   // (4, 512)
    xproj_gemm<<<g1, 256, GEMM_SMEM>>>(X, W_in);

    cudaFuncSetAttribute(rnn_scan,
                         cudaFuncAttributeMaxDynamicSharedMemorySize,
                         SCAN_SMEM);
    rnn_scan<<<128, 256, SCAN_SMEM>>>(W_h, b_h, out);
}

// round 11
// speedup vs baseline: 1.6616x; 1.1364x over previous
#include <cuda_runtime.h>
#include <cuda_bf16.h>
#include <cstdint>

#define T_STEPS 512
#define BATCH   128
#define DIM     512
#define M_ROWS  (T_STEPS * BATCH)   // 65536

typedef unsigned long long u64;

// Scratch
__device__ float g_xproj[(size_t)T_STEPS * BATCH * DIM];        // 134 MB
__device__ __nv_bfloat16 g_Xhi[(size_t)M_ROWS * DIM];           // 67 MB
__device__ __nv_bfloat16 g_Xlo[(size_t)M_ROWS * DIM];           // 67 MB
__device__ __nv_bfloat16 g_Whi[DIM * DIM];
__device__ __nv_bfloat16 g_Wlo[DIM * DIM];

// ---------------------------------------------------------------------------
// packed f32x2 helpers
// ---------------------------------------------------------------------------
__device__ __forceinline__ u64 pack2(float lo, float hi) {
    u64 r;
    asm("mov.b64 %0, {%1, %2};" : "=l"(r) : "f"(lo), "f"(hi));
    return r;
}
__device__ __forceinline__ void unpack2(u64 v, float& lo, float& hi) {
    asm("mov.b64 {%0, %1}, %2;" : "=f"(lo), "=f"(hi) : "l"(v));
}
__device__ __forceinline__ u64 ffma2(u64 a, u64 b, u64 c) {
    u64 d;
    asm("fma.rn.f32x2 %0, %1, %2, %3;" : "=l"(d) : "l"(a), "l"(b), "l"(c));
    return d;
}
__device__ __forceinline__ u64 fadd2(u64 a, u64 b) {
    u64 d;
    asm("add.rn.f32x2 %0, %1, %2;" : "=l"(d) : "l"(a), "l"(b));
    return d;
}

// ---------------------------------------------------------------------------
// mbarrier / st.async helpers (baseline sm_90 family features — compile OK)
// ---------------------------------------------------------------------------
__device__ __forceinline__ void mbar_init(uint32_t mb, uint32_t cnt) {
    asm volatile("mbarrier.init.shared.b64 [%0], %1;" :: "r"(mb), "r"(cnt)
                 : "memory");
}
__device__ __forceinline__ void mbar_expect_tx(uint32_t mb, uint32_t bytes) {
    asm volatile("mbarrier.arrive.expect_tx.shared.b64 _, [%0], %1;"
                 :: "r"(mb), "r"(bytes) : "memory");
}
__device__ __forceinline__ void mbar_wait_parity(uint32_t mb, uint32_t par) {
    uint32_t done;
    asm volatile(
        "{\n\t.reg .pred p;\n\t"
        "mbarrier.try_wait.parity.acquire.cta.shared::cta.b64 p, [%1], %2;\n\t"
        "selp.b32 %0, 1, 0, p;\n\t}"
        : "=r"(done) : "r"(mb), "r"(par) : "memory");
    if (!done) {
        asm volatile(
            "{\n\t.reg .pred P1;\n\t"
            "WAIT_LOOP_%=:\n\t"
            "mbarrier.try_wait.parity.acquire.cta.shared::cta.b64 P1, [%0], %1, 0x989680;\n\t"
            "@P1 bra.uni WAIT_DONE_%=;\n\t"
            "bra.uni WAIT_LOOP_%=;\n\t"
            "WAIT_DONE_%=:\n\t}"
            :: "r"(mb), "r"(par) : "memory");
    }
}
__device__ __forceinline__ void st_async_cluster_u64(uint32_t dst, u64 val,
                                                     uint32_t rmb) {
    asm volatile(
        "st.async.shared::cluster.mbarrier::complete_tx::bytes.b64 [%0], %1, [%2];"
        :: "r"(dst), "l"(val), "r"(rmb) : "memory");
}

// ---------------------------------------------------------------------------
// mma.sync / ldmatrix helpers (sm_80+ baseline — safe for compute_103)
// ---------------------------------------------------------------------------
__device__ __forceinline__ void ldsm_x4(uint32_t& r0, uint32_t& r1,
                                        uint32_t& r2, uint32_t& r3,
                                        uint32_t addr) {
    asm volatile("ldmatrix.sync.aligned.m8n8.x4.shared.b16 {%0,%1,%2,%3}, [%4];"
                 : "=r"(r0), "=r"(r1), "=r"(r2), "=r"(r3) : "r"(addr));
}
__device__ __forceinline__ void mma16816(float* d, const uint32_t* a,
                                         const uint32_t* b) {
    asm volatile(
        "mma.sync.aligned.m16n8k16.row.col.f32.bf16.bf16.f32 "
        "{%0,%1,%2,%3}, {%4,%5,%6,%7}, {%8,%9}, {%0,%1,%2,%3};"
        : "+f"(d[0]), "+f"(d[1]), "+f"(d[2]), "+f"(d[3])
        : "r"(a[0]), "r"(a[1]), "r"(a[2]), "r"(a[3]), "r"(b[0]), "r"(b[1]));
}
#define SWZ128(o) ((o) ^ (((o) >> 3) & 0x70))

// ============================================================================
// Kernel 0: fp32 -> bf16 hi/lo split
// ============================================================================
__global__ void split_kernel(const float* __restrict__ src,
                             __nv_bfloat162* __restrict__ hi,
                             __nv_bfloat162* __restrict__ lo, int n4) {
    int i = blockIdx.x * 256 + threadIdx.x;
    if (i >= n4) return;
    float4 v = ((const float4*)src)[i];
    __nv_bfloat16 hx = __float2bfloat16(v.x), hy = __float2bfloat16(v.y);
    __nv_bfloat16 hz = __float2bfloat16(v.z), hw = __float2bfloat16(v.w);
    __nv_bfloat16 lx = __float2bfloat16(v.x - __bfloat162float(hx));
    __nv_bfloat16 ly = __float2bfloat16(v.y - __bfloat162float(hy));
    __nv_bfloat16 lz = __float2bfloat16(v.z - __bfloat162float(hz));
    __nv_bfloat16 lw = __float2bfloat16(v.w - __bfloat162float(hw));
    hi[i * 2 + 0] = __nv_bfloat162(hx, hy);
    hi[i * 2 + 1] = __nv_bfloat162(hz, hw);
    lo[i * 2 + 0] = __nv_bfloat162(lx, ly);
    lo[i * 2 + 1] = __nv_bfloat162(lz, lw);
}

// ============================================================================
// Kernel 1: Xproj via mma.sync bf16 (3-split). 128x128 CTA tile, 8 warps at
// 32x64; SW128-swizzled stage of Ahi/Alo/Whi/Wlo [128x64 bf16] per k-chunk.
// ============================================================================
#define SM_AHI 0
#define SM_ALO 16384
#define SM_WHI 32768
#define SM_WLO 49152
#define GEMM2_SMEM 65536

__global__ void __launch_bounds__(256, 2)
xproj_mma(const __nv_bfloat16* __restrict__ Xhi,
          const __nv_bfloat16* __restrict__ Xlo,
          const __nv_bfloat16* __restrict__ Whi,
          const __nv_bfloat16* __restrict__ Wlo) {
    extern __shared__ __align__(1024) char sm[];
    const uint32_t smb = (uint32_t)__cvta_generic_to_shared(sm);
    const int tid  = threadIdx.x;
    const int lane = tid & 31;
    const int w    = tid >> 5;
    const int n0 = blockIdx.x * 128;
    const int m0 = blockIdx.y * 128;
    const int m_w = (w & 3) * 32;        // warp m offset in tile
    const int n_w = (w >> 2) * 64;       // warp n offset in tile

    float acc[2][8][4];
#pragma unroll
    for (int i = 0; i < 2; i++)
#pragma unroll
        for (int j = 0; j < 8; j++)
#pragma unroll
            for (int q = 0; q < 4; q++) acc[i][j][q] = 0.0f;

    const __nv_bfloat16* srcs[4] = {
        Xhi + (size_t)m0 * 512, Xlo + (size_t)m0 * 512,
        Whi + (size_t)n0 * 512, Wlo + (size_t)n0 * 512 };
    const uint32_t tgt_off[4] = { SM_AHI, SM_ALO, SM_WHI, SM_WLO };

    // precomputed ldmatrix address components
    // A (x4): row = m_w + mb*16 + (lane&15); xoff = (lane>>4)*16 + ks*32
    const int a_row_l = lane & 15;
    const int a_x_l   = (lane >> 4) * 16;
    // B (x4, covers 16 n): row = n_w + nb*16 + ((lane>>4)&1)*8 + (lane&7)
    //                      xoff = ((lane>>3)&1)*16 + ks*32
    const int b_row_l = ((lane >> 4) & 1) * 8 + (lane & 7);
    const int b_x_l   = ((lane >> 3) & 1) * 16;

    for (int c = 0; c < 8; c++) {
        const int kc = c * 64;
        // ---- stage 4 tiles [128 rows x 64 bf16] with SW128 swizzle ----
#pragma unroll
        for (int tgt = 0; tgt < 4; tgt++) {
#pragma unroll
            for (int i = 0; i < 4; i++) {
                const int idx = tid + i * 256;
                const int row = idx >> 3;
                const int cb  = (idx & 7) * 16;
                const char* gp =
                    (const char*)(srcs[tgt] + (size_t)row * 512 + kc) + cb;
                uint4 v = *(const uint4*)gp;
                uint32_t off = (uint32_t)(row * 128 + cb);
                *(uint4*)(sm + tgt_off[tgt] + SWZ128(off)) = v;
            }
        }
        __syncthreads();

        // ---- 3 split passes x 4 k16-steps ----
#pragma unroll
        for (int sp = 0; sp < 3; sp++) {
            const uint32_t abase = smb + (sp == 1 ? SM_ALO : SM_AHI);
            const uint32_t bbase = smb + (sp == 2 ? SM_WLO : SM_WHI);
#pragma unroll
            for (int ks = 0; ks < 4; ks++) {
                uint32_t afr[2][4];
#pragma unroll
                for (int mb = 0; mb < 2; mb++) {
                    const int row = m_w + mb * 16 + a_row_l;
                    const int x   = a_x_l + ks * 32;
                    uint32_t off = (uint32_t)(row * 128 +
                                              (x ^ ((row & 7) << 4)));
                    ldsm_x4(afr[mb][0], afr[mb][1], afr[mb][2], afr[mb][3],
                            abase + off);
                }
                uint32_t bfr[8][2];
#pragma unroll
                for (int pb = 0; pb < 4; pb++) {
                    const int row = n_w + pb * 16 + b_row_l;
                    const int x   = b_x_l + ks * 32;
                    uint32_t off = (uint32_t)(row * 128 +
                                              (x ^ ((row & 7) << 4)));
                    uint32_t r0, r1, r2, r3;
                    ldsm_x4(r0, r1, r2, r3, bbase + off);
                    bfr[pb * 2 + 0][0] = r0; bfr[pb * 2 + 0][1] = r1;
                    bfr[pb * 2 + 1][0] = r2; bfr[pb * 2 + 1][1] = r3;
                }
#pragma unroll
                for (int mb = 0; mb < 2; mb++)
#pragma unroll
                    for (int nb = 0; nb < 8; nb++)
                        mma16816(acc[mb][nb], afr[mb], bfr[nb]);
            }
        }
        __syncthreads();
    }

    // ---- epilogue: write fp32 D tile ----
    const int rbase = m0 + m_w + (lane >> 2);
    const int cbase = n0 + n_w + (lane & 3) * 2;
#pragma unroll
    for (int mb = 0; mb < 2; mb++) {
#pragma unroll
        for (int nb = 0; nb < 8; nb++) {
            float* p0 = g_xproj + (size_t)(rbase + mb * 16) * 512 + cbase + nb * 8;
            float* p1 = p0 + 8 * 512;
            *(float2*)p0 = make_float2(acc[mb][nb][0], acc[mb][nb][1]);
            *(float2*)p1 = make_float2(acc[mb][nb][2], acc[mb][nb][3]);
        }
    }
}

// ============================================================================
// Kernel 2: recurrent scan — UNCHANGED from R9 (best known).
// ============================================================================
#define HB_BUF_BYTES 16384
#define WT2_FLOATS   (64 * 512)
#define MBAR_OFF     ((WT2_FLOATS + 2 * 8 * 512) * 4)
#define SCAN_SMEM    (MBAR_OFF + 16)
#define TX_BYTES     16384u

#define RED2(OFF)                                                             \
    {                                                                         \
        const bool hi_ = (lane & (OFF)) != 0;                                 \
        _Pragma("unroll")                                                     \
        for (int i_ = 0; i_ < (OFF); i_++) {                                  \
            u64 send_ = hi_ ? acc2[i_] : acc2[i_ + (OFF)];                    \
            float sl_, sh_;                                                   \
            unpack2(send_, sl_, sh_);                                         \
            sl_ = __shfl_xor_sync(0xffffffffu, sl_, (OFF));                   \
            sh_ = __shfl_xor_sync(0xffffffffu, sh_, (OFF));                   \
            u64 keep_ = hi_ ? acc2[i_ + (OFF)] : acc2[i_];                    \
            acc2[i_] = fadd2(keep_, pack2(sl_, sh_));                         \
        }                                                                     \
    }

__global__ void __cluster_dims__(8, 1, 1) __launch_bounds__(256, 1)
rnn_scan(const float* __restrict__ Wh, const float* __restrict__ bh,
         float* __restrict__ out) {
    extern __shared__ __align__(16) float smem[];
    float* Wt = smem;
    float* hb = smem + WT2_FLOATS;

    const int tid  = threadIdx.x;
    const int lane = tid & 31;
    const int wid  = tid >> 5;
    const int r    = blockIdx.x & 7;
    const int g    = blockIdx.x >> 3;

    const uint32_t smem_u32 = (uint32_t)__cvta_generic_to_shared(smem);
    const uint32_t mb_u32   = smem_u32 + MBAR_OFF;

    for (int idx = tid; idx < 64 * 512 / 4; idx += 256) {
        int dl = idx >> 7;
        int k4 = (idx & 127) << 2;
        float4 v = __ldg((const float4*)(Wh + (size_t)(r * 64 + dl) * 512 + k4));
        float* wdst = Wt + (dl >> 1) * 1024 + (dl & 1);
        wdst[2 * (k4 + 0)] = v.x;
        wdst[2 * (k4 + 1)] = v.y;
        wdst[2 * (k4 + 2)] = v.z;
        wdst[2 * (k4 + 3)] = v.w;
    }
    {
        float4  z4  = make_float4(0.f, 0.f, 0.f, 0.f);
        float4* hd4 = (float4*)hb;
        for (int i = tid; i < 8 * 512 / 4; i += 256) hd4[i] = z4;
    }
    if (tid == 0) {
        mbar_init(mb_u32 + 0, 1);
        mbar_init(mb_u32 + 8, 1);
    }
    __syncthreads();
    asm volatile("barrier.cluster.arrive.aligned;" ::: "memory");
    asm volatile("barrier.cluster.wait.aligned;"   ::: "memory");
    if (tid == 0) {
        mbar_expect_tx(mb_u32 + 0, TX_BYTES);
        mbar_expect_tx(mb_u32 + 8, TX_BYTES);
    }
    asm volatile("barrier.cluster.arrive.aligned;" ::: "memory");
    asm volatile("barrier.cluster.wait.aligned;"   ::: "memory");

    const int bl    = lane >> 2;
    const int dl2   = (lane & 3) * 2;
    const int dglob = r * 64 + wid * 8 + dl2;
    const int bglob = g * 8 + bl;

    const u64 bias2 = pack2(bh[dglob], bh[dglob + 1]);
    const float* xp_ptr = g_xproj + (size_t)bglob * DIM + dglob;

    const uint32_t hb_u32 = smem_u32 + WT2_FLOATS * 4;
    const uint32_t slot_off = (uint32_t)(bl * 2048 + dglob * 4);
    uint32_t dst[8], rmb[8];
#pragma unroll
    for (int rr = 0; rr < 8; rr++) {
        asm("mapa.shared::cluster.u32 %0, %1, %2;"
            : "=r"(dst[rr]) : "r"(hb_u32 + slot_off), "r"(rr));
        asm("mapa.shared::cluster.u32 %0, %1, %2;"
            : "=r"(rmb[rr]) : "r"(mb_u32), "r"(rr));
    }

    const float* WtW = Wt + (size_t)(wid * 4) * 1024;

    float2 xp = *(const float2*)xp_ptr;
    uint32_t ph0 = 0, ph1 = 0;

    for (int t = 0; t < T_STEPS; t++) {
        const int p = t & 1;
        const float* hbp = hb + p * 4096;

        if (t > 0) {
            const uint32_t mb = mb_u32 + (uint32_t)p * 8;
            mbar_wait_parity(mb, p ? ph1 : ph0);
            if (p) ph1 ^= 1; else ph0 ^= 1;
            if (tid == 0) mbar_expect_tx(mb, TX_BYTES);
        }

        u64 acc2[32];
#pragma unroll
        for (int i = 0; i < 32; i++) acc2[i] = 0ull;

#pragma unroll 2
        for (int ki = 0; ki < 8; ki++) {
            const int k = ki * 64 + lane * 2;
            ulonglong2 wq[4];
#pragma unroll
            for (int dd = 0; dd < 4; dd++)
                wq[dd] = *(const ulonglong2*)(WtW + dd * 1024 + 2 * k);
#pragma unroll
            for (int b = 0; b < 8; b++) {
                float2 hv = *(const float2*)(hbp + b * 512 + k);
                u64 hd0 = pack2(hv.x, hv.x);
                u64 hd1 = pack2(hv.y, hv.y);
#pragma unroll
                for (int dd = 0; dd < 4; dd++) {
                    acc2[b * 4 + dd] = ffma2(hd0, wq[dd].x, acc2[b * 4 + dd]);
                    acc2[b * 4 + dd] = ffma2(hd1, wq[dd].y, acc2[b * 4 + dd]);
                }
            }
        }

        RED2(16) RED2(8) RED2(4) RED2(2) RED2(1)

        u64 z2 = fadd2(fadd2(acc2[0], pack2(xp.x, xp.y)), bias2);
        float z0, z1;
        unpack2(z2, z0, z1);
        const float h0 = 1.0f / (1.0f + __expf(-z0));
        const float h1 = 1.0f / (1.0f + __expf(-z1));
        const u64 hh = pack2(h0, h1);

        if (t < T_STEPS - 1) {
            const int q = p ^ 1;
            const uint32_t boff = (uint32_t)(q * HB_BUF_BYTES);
            const uint32_t moff = (uint32_t)(q * 8);
#pragma unroll
            for (int rr = 0; rr < 8; rr++)
                st_async_cluster_u64(dst[rr] + boff, hh, rmb[rr] + moff);
            xp = __ldg((const float2*)(xp_ptr + (size_t)(t + 1) * BATCH * DIM));
        } else {
            *(float2*)(out + (size_t)bglob * DIM + dglob) = make_float2(h0, h1);
        }
    }

    asm volatile("barrier.cluster.arrive.aligned;" ::: "memory");
    asm volatile("barrier.cluster.wait.aligned;"   ::: "memory");
}

// ============================================================================
extern "C" void kernel_launch(void* const* d_in, const int* in_sizes, int n_in,
                              void* d_out, int out_size) {
    const float* X    = (const float*)d_in[0];  // [512,128,512]
    const float* W_in = (const float*)d_in[1];  // [512,512]
    const float* W_h  = (const float*)d_in[2];  // [512,512]
    const float* b_h  = (const float*)d_in[3];  // [512]
    float* out = (float*)d_out;                 // [128,512]

    (void)in_sizes; (void)n_in; (void)out_size;

    __nv_bfloat162 *xhi, *xlo, *whi, *wlo;
    cudaGetSymbolAddress((void**)&xhi, g_Xhi);
    cudaGetSymbolAddress((void**)&xlo, g_Xlo);
    cudaGetSymbolAddress((void**)&whi, g_Whi);
    cudaGetSymbolAddress((void**)&wlo, g_Wlo);

    // 0) split X and W_in into bf16 hi/lo
    split_kernel<<<(M_ROWS * DIM / 4 + 255) / 256, 256>>>(X, xhi, xlo,
                                                          M_ROWS * DIM / 4);
    split_kernel<<<(DIM * DIM / 4 + 255) / 256, 256>>>(W_in, whi, wlo,
                                                       DIM * DIM / 4);

    // 1) Xproj via mma.sync bf16 (3-split)
    cudaFuncSetAttribute(xproj_mma,
                         cudaFuncAttributeMaxDynamicSharedMemorySize,
                         GEMM2_SMEM);
    dim3 g1(DIM / 128, M_ROWS / 128);   // (4, 512)
    xproj_mma<<<g1, 256, GEMM2_SMEM>>>(
        (const __nv_bfloat16*)xhi, (const __nv_bfloat16*)xlo,
        (const __nv_bfloat16*)whi, (const __nv_bfloat16*)wlo);

    // 2) recurrent scan (unchanged R9)
    cudaFuncSetAttribute(rnn_scan,
                         cudaFuncAttributeMaxDynamicSharedMemorySize,
                         SCAN_SMEM);
    rnn_scan<<<128, 256, SCAN_SMEM>>>(W_h, b_h, out);
}

// round 13
// speedup vs baseline: 2.1902x; 1.3181x over previous
#include <cuda_runtime.h>
#include <cuda_bf16.h>
#include <cstdint>

#define T_STEPS 512
#define BATCH   128
#define DIM     512
#define M_ROWS  (T_STEPS * BATCH)   // 65536

typedef unsigned long long u64;

// Scratch
__device__ float g_xproj[(size_t)T_STEPS * BATCH * DIM];        // 134 MB
__device__ __nv_bfloat16 g_Xhi[(size_t)M_ROWS * DIM];           // 67 MB
__device__ __nv_bfloat16 g_Xlo[(size_t)M_ROWS * DIM];           // 67 MB
__device__ __nv_bfloat16 g_Whi[DIM * DIM];
__device__ __nv_bfloat16 g_Wlo[DIM * DIM];

// ---------------------------------------------------------------------------
// helpers
// ---------------------------------------------------------------------------
__device__ __forceinline__ void split2(float x, float y,
                                       uint32_t& hi, uint32_t& lo) {
    __nv_bfloat16 hx = __float2bfloat16(x), hy = __float2bfloat16(y);
    float rx = x - __bfloat162float(hx);
    float ry = y - __bfloat162float(hy);
    __nv_bfloat162 h2(hx, hy);
    __nv_bfloat162 l2(__float2bfloat16(rx), __float2bfloat16(ry));
    hi = *reinterpret_cast<uint32_t*>(&h2);
    lo = *reinterpret_cast<uint32_t*>(&l2);
}
__device__ __forceinline__ u64 cellpack(float a, float b) {
    uint32_t hi, lo;
    split2(a, b, hi, lo);
    return (u64)hi | ((u64)lo << 32);
}

// mbarrier / st.async (baseline features, proven in R9/R11)
__device__ __forceinline__ void mbar_init(uint32_t mb, uint32_t cnt) {
    asm volatile("mbarrier.init.shared.b64 [%0], %1;" :: "r"(mb), "r"(cnt)
                 : "memory");
}
__device__ __forceinline__ void mbar_expect_tx(uint32_t mb, uint32_t bytes) {
    asm volatile("mbarrier.arrive.expect_tx.shared.b64 _, [%0], %1;"
                 :: "r"(mb), "r"(bytes) : "memory");
}
__device__ __forceinline__ void mbar_wait_parity(uint32_t mb, uint32_t par) {
    uint32_t done;
    asm volatile(
        "{\n\t.reg .pred p;\n\t"
        "mbarrier.try_wait.parity.acquire.cta.shared::cta.b64 p, [%1], %2;\n\t"
        "selp.b32 %0, 1, 0, p;\n\t}"
        : "=r"(done) : "r"(mb), "r"(par) : "memory");
    if (!done) {
        asm volatile(
            "{\n\t.reg .pred P1;\n\t"
            "WAIT_LOOP_%=:\n\t"
            "mbarrier.try_wait.parity.acquire.cta.shared::cta.b64 P1, [%0], %1, 0x989680;\n\t"
            "@P1 bra.uni WAIT_DONE_%=;\n\t"
            "bra.uni WAIT_LOOP_%=;\n\t"
            "WAIT_DONE_%=:\n\t}"
            :: "r"(mb), "r"(par) : "memory");
    }
}
__device__ __forceinline__ void st_async_cluster_u64(uint32_t dst, u64 val,
                                                     uint32_t rmb) {
    asm volatile(
        "st.async.shared::cluster.mbarrier::complete_tx::bytes.b64 [%0], %1, [%2];"
        :: "r"(dst), "l"(val), "r"(rmb) : "memory");
}

// mma.sync / ldmatrix (sm_80+ baseline; validated in R11)
__device__ __forceinline__ void ldsm_x4(uint32_t& r0, uint32_t& r1,
                                        uint32_t& r2, uint32_t& r3,
                                        uint32_t addr) {
    asm volatile("ldmatrix.sync.aligned.m8n8.x4.shared.b16 {%0,%1,%2,%3}, [%4];"
                 : "=r"(r0), "=r"(r1), "=r"(r2), "=r"(r3) : "r"(addr));
}
__device__ __forceinline__ void mma16816(float* d, const uint32_t* a,
                                         const uint32_t* b) {
    asm volatile(
        "mma.sync.aligned.m16n8k16.row.col.f32.bf16.bf16.f32 "
        "{%0,%1,%2,%3}, {%4,%5,%6,%7}, {%8,%9}, {%0,%1,%2,%3};"
        : "+f"(d[0]), "+f"(d[1]), "+f"(d[2]), "+f"(d[3])
        : "r"(a[0]), "r"(a[1]), "r"(a[2]), "r"(a[3]), "r"(b[0]), "r"(b[1]));
}
#define SWZ128(o) ((o) ^ (((o) >> 3) & 0x70))

// ============================================================================
// Kernel 0: fp32 -> bf16 hi/lo split
// ============================================================================
__global__ void split_kernel(const float* __restrict__ src,
                             __nv_bfloat162* __restrict__ hi,
                             __nv_bfloat162* __restrict__ lo, int n4) {
    int i = blockIdx.x * 256 + threadIdx.x;
    if (i >= n4) return;
    float4 v = ((const float4*)src)[i];
    uint32_t h0, l0, h1, l1;
    split2(v.x, v.y, h0, l0);
    split2(v.z, v.w, h1, l1);
    *(uint32_t*)&hi[i * 2 + 0] = h0;
    *(uint32_t*)&hi[i * 2 + 1] = h1;
    *(uint32_t*)&lo[i * 2 + 0] = l0;
    *(uint32_t*)&lo[i * 2 + 1] = l1;
}

// ============================================================================
// Kernel 1: Xproj via mma.sync bf16 3-split — UNCHANGED from R11 (passed).
// ============================================================================
#define SM_AHI 0
#define SM_ALO 16384
#define SM_WHI 32768
#define SM_WLO 49152
#define GEMM2_SMEM 65536

__global__ void __launch_bounds__(256, 2)
xproj_mma(const __nv_bfloat16* __restrict__ Xhi,
          const __nv_bfloat16* __restrict__ Xlo,
          const __nv_bfloat16* __restrict__ Whi,
          const __nv_bfloat16* __restrict__ Wlo) {
    extern __shared__ __align__(1024) char sm[];
    const uint32_t smb = (uint32_t)__cvta_generic_to_shared(sm);
    const int tid  = threadIdx.x;
    const int lane = tid & 31;
    const int w    = tid >> 5;
    const int n0 = blockIdx.x * 128;
    const int m0 = blockIdx.y * 128;
    const int m_w = (w & 3) * 32;
    const int n_w = (w >> 2) * 64;

    float acc[2][8][4];
#pragma unroll
    for (int i = 0; i < 2; i++)
#pragma unroll
        for (int j = 0; j < 8; j++)
#pragma unroll
            for (int q = 0; q < 4; q++) acc[i][j][q] = 0.0f;

    const __nv_bfloat16* srcs[4] = {
        Xhi + (size_t)m0 * 512, Xlo + (size_t)m0 * 512,
        Whi + (size_t)n0 * 512, Wlo + (size_t)n0 * 512 };
    const uint32_t tgt_off[4] = { SM_AHI, SM_ALO, SM_WHI, SM_WLO };

    const int a_row_l = lane & 15;
    const int a_x_l   = (lane >> 4) * 16;
    const int b_row_l = ((lane >> 4) & 1) * 8 + (lane & 7);
    const int b_x_l   = ((lane >> 3) & 1) * 16;

    for (int c = 0; c < 8; c++) {
        const int kc = c * 64;
#pragma unroll
        for (int tgt = 0; tgt < 4; tgt++) {
#pragma unroll
            for (int i = 0; i < 4; i++) {
                const int idx = tid + i * 256;
                const int row = idx >> 3;
                const int cb  = (idx & 7) * 16;
                const char* gp =
                    (const char*)(srcs[tgt] + (size_t)row * 512 + kc) + cb;
                uint4 v = *(const uint4*)gp;
                uint32_t off = (uint32_t)(row * 128 + cb);
                *(uint4*)(sm + tgt_off[tgt] + SWZ128(off)) = v;
            }
        }
        __syncthreads();

#pragma unroll
        for (int sp = 0; sp < 3; sp++) {
            const uint32_t abase = smb + (sp == 1 ? SM_ALO : SM_AHI);
            const uint32_t bbase = smb + (sp == 2 ? SM_WLO : SM_WHI);
#pragma unroll
            for (int ks = 0; ks < 4; ks++) {
                uint32_t afr[2][4];
#pragma unroll
                for (int mb = 0; mb < 2; mb++) {
                    const int row = m_w + mb * 16 + a_row_l;
                    const int x   = a_x_l + ks * 32;
                    uint32_t off = (uint32_t)(row * 128 +
                                              (x ^ ((row & 7) << 4)));
                    ldsm_x4(afr[mb][0], afr[mb][1], afr[mb][2], afr[mb][3],
                            abase + off);
                }
                uint32_t bfr[8][2];
#pragma unroll
                for (int pb = 0; pb < 4; pb++) {
                    const int row = n_w + pb * 16 + b_row_l;
                    const int x   = b_x_l + ks * 32;
                    uint32_t off = (uint32_t)(row * 128 +
                                              (x ^ ((row & 7) << 4)));
                    uint32_t r0, r1, r2, r3;
                    ldsm_x4(r0, r1, r2, r3, bbase + off);
                    bfr[pb * 2 + 0][0] = r0; bfr[pb * 2 + 0][1] = r1;
                    bfr[pb * 2 + 1][0] = r2; bfr[pb * 2 + 1][1] = r3;
                }
#pragma unroll
                for (int mb = 0; mb < 2; mb++)
#pragma unroll
                    for (int nb = 0; nb < 8; nb++)
                        mma16816(acc[mb][nb], afr[mb], bfr[nb]);
            }
        }
        __syncthreads();
    }

    const int rbase = m0 + m_w + (lane >> 2);
    const int cbase = n0 + n_w + (lane & 3) * 2;
#pragma unroll
    for (int mb = 0; mb < 2; mb++) {
#pragma unroll
        for (int nb = 0; nb < 8; nb++) {
            float* p0 = g_xproj + (size_t)(rbase + mb * 16) * 512 + cbase + nb * 8;
            float* p1 = p0 + 8 * 512;
            *(float2*)p0 = make_float2(acc[mb][nb][0], acc[mb][nb][1]);
            *(float2*)p1 = make_float2(acc[mb][nb][2], acc[mb][nb][3]);
        }
    }
}

// ============================================================================
// Kernel 2: recurrent scan via mma.sync with register-resident W_h.
// IDENTICAL to R12 except rowoff(): the (b>>2)*4 bank-fix broke the 8-byte
// alignment of st.async.b64 for batch rows 4 and 6 -> "misaligned address".
// Now rowoff(b) = b*2080 (8B-aligned); accepts a 2-way LDS bank conflict
// between rows {r, r+4} (~64 cyc/step, overlapped with HMMA).
// ============================================================================
#define HC_BSTRIDE  2080            // byte stride between batch rows
#define HC_BUF      16640           // one h buffer (8 rows x 2080)
#define STG_OFF     (2 * HC_BUF)    // 33280
#define MBAR_OFF2   (STG_OFF + 2048)// 35328
#define SCAN_SMEM   (MBAR_OFF2 + 32)
#define TX_BYTES    16384u

__device__ __forceinline__ int rowoff(int b) {
    return b * HC_BSTRIDE;          // multiple of 8 for every row
}

__global__ void __cluster_dims__(8, 1, 1) __launch_bounds__(256, 1)
rnn_scan(const float* __restrict__ Wh, const float* __restrict__ bh,
         float* __restrict__ out) {
    extern __shared__ __align__(16) char sm[];
    char*  hc  = sm;                          // [2][HC_BUF] h cells
    float* stg = (float*)(sm + STG_OFF);      // [4][32] float4 staging

    const int tid   = threadIdx.x;
    const int lane  = tid & 31;
    const int w     = tid >> 5;
    const int j     = w >> 1;        // m-block 0..3
    const int kh    = w & 1;         // k-half
    const int rk    = blockIdx.x & 7;    // cluster rank -> dim slice
    const int g     = blockIdx.x >> 3;   // batch group
    const int row_l = lane >> 2;     // 0..7 (A-row low / B-n)
    const int qb    = lane & 3;

    const uint32_t smb     = (uint32_t)__cvta_generic_to_shared(sm);
    const uint32_t mb_u32  = smb + MBAR_OFF2;

    const int d_base = rk * 64 + j * 16;

    // ---- W_h fragments into registers (bf16 hi/lo split), one-time ----
    uint32_t whi[16][4], wlo[16][4];
    {
        const float* Wr0 = Wh + (size_t)(d_base + row_l) * 512 + kh * 256;
        const float* Wr1 = Wr0 + 8 * 512;
#pragma unroll
        for (int ks = 0; ks < 16; ks++) {
            const int k0 = ks * 16 + qb * 2;
            float2 q00 = *(const float2*)(Wr0 + k0);
            float2 q10 = *(const float2*)(Wr1 + k0);
            float2 q01 = *(const float2*)(Wr0 + k0 + 8);
            float2 q11 = *(const float2*)(Wr1 + k0 + 8);
            split2(q00.x, q00.y, whi[ks][0], wlo[ks][0]);
            split2(q10.x, q10.y, whi[ks][1], wlo[ks][1]);
            split2(q01.x, q01.y, whi[ks][2], wlo[ks][2]);
            split2(q11.x, q11.y, whi[ks][3], wlo[ks][3]);
        }
    }

    // ---- zero h buffer 0 (t=0 reads zeros) ----
    for (int i = tid; i < HC_BUF / 8; i += 256) ((u64*)hc)[i] = 0ull;
    if (tid == 0) {
        mbar_init(mb_u32 + 0, 1);
        mbar_init(mb_u32 + 8, 1);
    }
    __syncthreads();
    asm volatile("barrier.cluster.arrive.aligned;" ::: "memory");
    asm volatile("barrier.cluster.wait.aligned;"   ::: "memory");
    if (tid == 0) {
        mbar_expect_tx(mb_u32 + 0, TX_BYTES);
        mbar_expect_tx(mb_u32 + 8, TX_BYTES);
    }
    asm volatile("barrier.cluster.arrive.aligned;" ::: "memory");
    asm volatile("barrier.cluster.wait.aligned;"   ::: "memory");

    // ---- B-frag read base: batch row = row_l, k-pair = kh*128 + ks*8 + qb --
    const char* hbase = hc + rowoff(row_l) + (kh * 128 + qb) * 8;

    // ---- output/push mapping (even warps own final D after reduce) ----
    const int b0l   = qb * 2;                     // local batch pair
    const int bgl0  = g * 8 + b0l;
    const float bias0 = bh[d_base + row_l];
    const float bias1 = bh[d_base + row_l + 8];
    const float* xpb = g_xproj + ((size_t)bgl0 * 512 + d_base + row_l);

    // push destinations (even-r lanes of even warps): cell (b0l, dpA)
    const int dpA = rk * 32 + j * 8 + (row_l >> 1);
    uint32_t dst[8], rmb[8];
#pragma unroll
    for (int rr = 0; rr < 8; rr++) {
        asm("mapa.shared::cluster.u32 %0, %1, %2;"
            : "=r"(dst[rr])
            : "r"(smb + (uint32_t)(rowoff(b0l) + dpA * 8)), "r"(rr));
        asm("mapa.shared::cluster.u32 %0, %1, %2;"
            : "=r"(rmb[rr]) : "r"(mb_u32), "r"(rr));
    }

    // prefetch xp(0)
    float xq0 = 0.f, xq1 = 0.f, xq2 = 0.f, xq3 = 0.f;
    if (!kh) {
        xq0 = __ldg(xpb);        xq1 = __ldg(xpb + 512);
        xq2 = __ldg(xpb + 8);    xq3 = __ldg(xpb + 520);
    }

    uint32_t ph0 = 0, ph1 = 0;

    for (int t = 0; t < T_STEPS; t++) {
        const int p = t & 1;

        if (t > 0) {
            const uint32_t mb = mb_u32 + (uint32_t)p * 8;
            mbar_wait_parity(mb, p ? ph1 : ph0);
            if (p) ph1 ^= 1; else ph0 ^= 1;
            if (tid == 0) mbar_expect_tx(mb, TX_BYTES);
        }

        // ---- mma over this warp's k-half ----
        float dacc[4] = {0.f, 0.f, 0.f, 0.f};
        const char* hp = hbase + p * HC_BUF;
#pragma unroll
        for (int ks = 0; ks < 16; ks++) {
            const char* cp = hp + ks * 64;
            uint32_t bhv[2], blv[2];
            bhv[0] = *(const uint32_t*)(cp);
            blv[0] = *(const uint32_t*)(cp + 4);
            bhv[1] = *(const uint32_t*)(cp + 32);
            blv[1] = *(const uint32_t*)(cp + 36);
            mma16816(dacc, whi[ks], bhv);
            mma16816(dacc, wlo[ks], bhv);
            mma16816(dacc, whi[ks], blv);
        }

        // ---- k-half pair reduce via staging ----
        if (kh) {
            ((float4*)stg)[j * 32 + lane] =
                make_float4(dacc[0], dacc[1], dacc[2], dacc[3]);
        }
        __syncthreads();

        if (!kh) {
            float4 o = ((float4*)stg)[j * 32 + lane];
            const float z0 = dacc[0] + o.x + xq0 + bias0;  // (r,   b0)
            const float z1 = dacc[1] + o.y + xq1 + bias0;  // (r,   b1)
            const float z2 = dacc[2] + o.z + xq2 + bias1;  // (r+8, b0)
            const float z3 = dacc[3] + o.w + xq3 + bias1;
            const float h0 = 1.0f / (1.0f + __expf(-z0));
            const float h1 = 1.0f / (1.0f + __expf(-z1));
            const float h2 = 1.0f / (1.0f + __expf(-z2));
            const float h3 = 1.0f / (1.0f + __expf(-z3));

            if (t < T_STEPS - 1) {
                // partner (d+1) values live at lane+4 (row_l+1)
                const float n0 = __shfl_down_sync(0xffffffffu, h0, 4);
                const float n1 = __shfl_down_sync(0xffffffffu, h1, 4);
                const float n2 = __shfl_down_sync(0xffffffffu, h2, 4);
                const float n3 = __shfl_down_sync(0xffffffffu, h3, 4);
                if (!(row_l & 1)) {
                    const u64 cA0 = cellpack(h0, n0);   // (b0, dpA)
                    const u64 cA1 = cellpack(h1, n1);   // (b1, dpA)
                    const u64 cB0 = cellpack(h2, n2);   // (b0, dpA+4)
                    const u64 cB1 = cellpack(h3, n3);
                    const uint32_t qo = (uint32_t)((p ^ 1) * HC_BUF);
#pragma unroll
                    for (int rr = 0; rr < 8; rr++) {
                        const uint32_t d0 = dst[rr] + qo;
                        const uint32_t m0_ = rmb[rr] + (uint32_t)((p ^ 1) * 8);
                        st_async_cluster_u64(d0, cA0, m0_);
                        st_async_cluster_u64(d0 + HC_BSTRIDE, cA1, m0_);
                        st_async_cluster_u64(d0 + 32, cB0, m0_);
                        st_async_cluster_u64(d0 + HC_BSTRIDE + 32, cB1, m0_);
                    }
                }
                // prefetch xp(t+1)
                const float* xn = xpb + (size_t)(t + 1) * BATCH * DIM;
                xq0 = __ldg(xn);      xq1 = __ldg(xn + 512);
                xq2 = __ldg(xn + 8);  xq3 = __ldg(xn + 520);
            } else {
                float* ob = out + (size_t)bgl0 * 512 + d_base + row_l;
                ob[0]       = h0;
                ob[512]     = h1;
                ob[8]       = h2;
                ob[520]     = h3;
            }
        }
    }

    // keep cluster alive for in-flight async stores
    asm volatile("barrier.cluster.arrive.aligned;" ::: "memory");
    asm volatile("barrier.cluster.wait.aligned;"   ::: "memory");
}

// ============================================================================
extern "C" void kernel_launch(void* const* d_in, const int* in_sizes, int n_in,
                              void* d_out, int out_size) {
    const float* X    = (const float*)d_in[0];  // [512,128,512]
    const float* W_in = (const float*)d_in[1];  // [512,512]
    const float* W_h  = (const float*)d_in[2];  // [512,512]
    const float* b_h  = (const float*)d_in[3];  // [512]
    float* out = (float*)d_out;                 // [128,512]

    (void)in_sizes; (void)n_in; (void)out_size;

    __nv_bfloat162 *xhi, *xlo, *whi, *wlo;
    cudaGetSymbolAddress((void**)&xhi, g_Xhi);
    cudaGetSymbolAddress((void**)&xlo, g_Xlo);
    cudaGetSymbolAddress((void**)&whi, g_Whi);
    cudaGetSymbolAddress((void**)&wlo, g_Wlo);

    // 0) split X and W_in into bf16 hi/lo
    split_kernel<<<(M_ROWS * DIM / 4 + 255) / 256, 256>>>(X, xhi, xlo,
                                                          M_ROWS * DIM / 4);
    split_kernel<<<(DIM * DIM / 4 + 255) / 256, 256>>>(W_in, whi, wlo,
                                                       DIM * DIM / 4);

    // 1) Xproj via mma.sync bf16 (3-split)
    cudaFuncSetAttribute(xproj_mma,
                         cudaFuncAttributeMaxDynamicSharedMemorySize,
                         GEMM2_SMEM);
    dim3 g1(DIM / 128, M_ROWS / 128);   // (4, 512)
    xproj_mma<<<g1, 256, GEMM2_SMEM>>>(
        (const __nv_bfloat16*)xhi, (const __nv_bfloat16*)xlo,
        (const __nv_bfloat16*)whi, (const __nv_bfloat16*)wlo);

    // 2) recurrent scan via mma.sync (register-resident W_h)
    rnn_scan<<<128, 256, SCAN_SMEM>>>(W_h, b_h, out);
}

// round 14
// speedup vs baseline: 2.2580x; 1.0310x over previous
#include <cuda_runtime.h>
#include <cuda_bf16.h>
#include <cstdint>

#define T_STEPS 512
#define BATCH   128
#define DIM     512
#define M_ROWS  (T_STEPS * BATCH)   // 65536

typedef unsigned long long u64;

// Scratch
__device__ float g_xproj[(size_t)T_STEPS * BATCH * DIM];        // 134 MB
__device__ __nv_bfloat16 g_Xhi[(size_t)M_ROWS * DIM];           // 67 MB
__device__ __nv_bfloat16 g_Xlo[(size_t)M_ROWS * DIM];           // 67 MB
__device__ __nv_bfloat16 g_Whi[DIM * DIM];
__device__ __nv_bfloat16 g_Wlo[DIM * DIM];

// ---------------------------------------------------------------------------
// helpers
// ---------------------------------------------------------------------------
__device__ __forceinline__ void split2(float x, float y,
                                       uint32_t& hi, uint32_t& lo) {
    __nv_bfloat16 hx = __float2bfloat16(x), hy = __float2bfloat16(y);
    float rx = x - __bfloat162float(hx);
    float ry = y - __bfloat162float(hy);
    __nv_bfloat162 h2(hx, hy);
    __nv_bfloat162 l2(__float2bfloat16(rx), __float2bfloat16(ry));
    hi = *reinterpret_cast<uint32_t*>(&h2);
    lo = *reinterpret_cast<uint32_t*>(&l2);
}
__device__ __forceinline__ u64 cellpack(float a, float b) {
    uint32_t hi, lo;
    split2(a, b, hi, lo);
    return (u64)hi | ((u64)lo << 32);
}

// mbarrier / st.async (baseline features, proven in R9/R11/R13)
__device__ __forceinline__ void mbar_init(uint32_t mb, uint32_t cnt) {
    asm volatile("mbarrier.init.shared.b64 [%0], %1;" :: "r"(mb), "r"(cnt)
                 : "memory");
}
__device__ __forceinline__ void mbar_expect_tx(uint32_t mb, uint32_t bytes) {
    asm volatile("mbarrier.arrive.expect_tx.shared.b64 _, [%0], %1;"
                 :: "r"(mb), "r"(bytes) : "memory");
}
__device__ __forceinline__ void mbar_wait_parity(uint32_t mb, uint32_t par) {
    uint32_t done;
    asm volatile(
        "{\n\t.reg .pred p;\n\t"
        "mbarrier.try_wait.parity.acquire.cta.shared::cta.b64 p, [%1], %2;\n\t"
        "selp.b32 %0, 1, 0, p;\n\t}"
        : "=r"(done) : "r"(mb), "r"(par) : "memory");
    if (!done) {
        asm volatile(
            "{\n\t.reg .pred P1;\n\t"
            "WAIT_LOOP_%=:\n\t"
            "mbarrier.try_wait.parity.acquire.cta.shared::cta.b64 P1, [%0], %1, 0x989680;\n\t"
            "@P1 bra.uni WAIT_DONE_%=;\n\t"
            "bra.uni WAIT_LOOP_%=;\n\t"
            "WAIT_DONE_%=:\n\t}"
            :: "r"(mb), "r"(par) : "memory");
    }
}
__device__ __forceinline__ void st_async_cluster_u64(uint32_t dst, u64 val,
                                                     uint32_t rmb) {
    asm volatile(
        "st.async.shared::cluster.mbarrier::complete_tx::bytes.b64 [%0], %1, [%2];"
        :: "r"(dst), "l"(val), "r"(rmb) : "memory");
}

// mma.sync / ldmatrix (sm_80+ baseline; validated in R11/R13)
__device__ __forceinline__ void ldsm_x4(uint32_t& r0, uint32_t& r1,
                                        uint32_t& r2, uint32_t& r3,
                                        uint32_t addr) {
    asm volatile("ldmatrix.sync.aligned.m8n8.x4.shared.b16 {%0,%1,%2,%3}, [%4];"
                 : "=r"(r0), "=r"(r1), "=r"(r2), "=r"(r3) : "r"(addr));
}
__device__ __forceinline__ void mma16816(float* d, const uint32_t* a,
                                         const uint32_t* b) {
    asm volatile(
        "mma.sync.aligned.m16n8k16.row.col.f32.bf16.bf16.f32 "
        "{%0,%1,%2,%3}, {%4,%5,%6,%7}, {%8,%9}, {%0,%1,%2,%3};"
        : "+f"(d[0]), "+f"(d[1]), "+f"(d[2]), "+f"(d[3])
        : "r"(a[0]), "r"(a[1]), "r"(a[2]), "r"(a[3]), "r"(b[0]), "r"(b[1]));
}
#define SWZ128(o) ((o) ^ (((o) >> 3) & 0x70))

// ============================================================================
// Kernel 0: fp32 -> bf16 hi/lo split
// ============================================================================
__global__ void split_kernel(const float* __restrict__ src,
                             __nv_bfloat162* __restrict__ hi,
                             __nv_bfloat162* __restrict__ lo, int n4) {
    int i = blockIdx.x * 256 + threadIdx.x;
    if (i >= n4) return;
    float4 v = ((const float4*)src)[i];
    uint32_t h0, l0, h1, l1;
    split2(v.x, v.y, h0, l0);
    split2(v.z, v.w, h1, l1);
    *(uint32_t*)&hi[i * 2 + 0] = h0;
    *(uint32_t*)&hi[i * 2 + 1] = h1;
    *(uint32_t*)&lo[i * 2 + 0] = l0;
    *(uint32_t*)&lo[i * 2 + 1] = l1;
}

// ============================================================================
// Kernel 1: Xproj via mma.sync bf16 3-split — UNCHANGED from R11/R13.
// ============================================================================
#define SM_AHI 0
#define SM_ALO 16384
#define SM_WHI 32768
#define SM_WLO 49152
#define GEMM2_SMEM 65536

__global__ void __launch_bounds__(256, 2)
xproj_mma(const __nv_bfloat16* __restrict__ Xhi,
          const __nv_bfloat16* __restrict__ Xlo,
          const __nv_bfloat16* __restrict__ Whi,
          const __nv_bfloat16* __restrict__ Wlo) {
    extern __shared__ __align__(1024) char sm[];
    const uint32_t smb = (uint32_t)__cvta_generic_to_shared(sm);
    const int tid  = threadIdx.x;
    const int lane = tid & 31;
    const int w    = tid >> 5;
    const int n0 = blockIdx.x * 128;
    const int m0 = blockIdx.y * 128;
    const int m_w = (w & 3) * 32;
    const int n_w = (w >> 2) * 64;

    float acc[2][8][4];
#pragma unroll
    for (int i = 0; i < 2; i++)
#pragma unroll
        for (int j = 0; j < 8; j++)
#pragma unroll
            for (int q = 0; q < 4; q++) acc[i][j][q] = 0.0f;

    const __nv_bfloat16* srcs[4] = {
        Xhi + (size_t)m0 * 512, Xlo + (size_t)m0 * 512,
        Whi + (size_t)n0 * 512, Wlo + (size_t)n0 * 512 };
    const uint32_t tgt_off[4] = { SM_AHI, SM_ALO, SM_WHI, SM_WLO };

    const int a_row_l = lane & 15;
    const int a_x_l   = (lane >> 4) * 16;
    const int b_row_l = ((lane >> 4) & 1) * 8 + (lane & 7);
    const int b_x_l   = ((lane >> 3) & 1) * 16;

    for (int c = 0; c < 8; c++) {
        const int kc = c * 64;
#pragma unroll
        for (int tgt = 0; tgt < 4; tgt++) {
#pragma unroll
            for (int i = 0; i < 4; i++) {
                const int idx = tid + i * 256;
                const int row = idx >> 3;
                const int cb  = (idx & 7) * 16;
                const char* gp =
                    (const char*)(srcs[tgt] + (size_t)row * 512 + kc) + cb;
                uint4 v = *(const uint4*)gp;
                uint32_t off = (uint32_t)(row * 128 + cb);
                *(uint4*)(sm + tgt_off[tgt] + SWZ128(off)) = v;
            }
        }
        __syncthreads();

#pragma unroll
        for (int sp = 0; sp < 3; sp++) {
            const uint32_t abase = smb + (sp == 1 ? SM_ALO : SM_AHI);
            const uint32_t bbase = smb + (sp == 2 ? SM_WLO : SM_WHI);
#pragma unroll
            for (int ks = 0; ks < 4; ks++) {
                uint32_t afr[2][4];
#pragma unroll
                for (int mb = 0; mb < 2; mb++) {
                    const int row = m_w + mb * 16 + a_row_l;
                    const int x   = a_x_l + ks * 32;
                    uint32_t off = (uint32_t)(row * 128 +
                                              (x ^ ((row & 7) << 4)));
                    ldsm_x4(afr[mb][0], afr[mb][1], afr[mb][2], afr[mb][3],
                            abase + off);
                }
                uint32_t bfr[8][2];
#pragma unroll
                for (int pb = 0; pb < 4; pb++) {
                    const int row = n_w + pb * 16 + b_row_l;
                    const int x   = b_x_l + ks * 32;
                    uint32_t off = (uint32_t)(row * 128 +
                                              (x ^ ((row & 7) << 4)));
                    uint32_t r0, r1, r2, r3;
                    ldsm_x4(r0, r1, r2, r3, bbase + off);
                    bfr[pb * 2 + 0][0] = r0; bfr[pb * 2 + 0][1] = r1;
                    bfr[pb * 2 + 1][0] = r2; bfr[pb * 2 + 1][1] = r3;
                }
#pragma unroll
                for (int mb = 0; mb < 2; mb++)
#pragma unroll
                    for (int nb = 0; nb < 8; nb++)
                        mma16816(acc[mb][nb], afr[mb], bfr[nb]);
            }
        }
        __syncthreads();
    }

    const int rbase = m0 + m_w + (lane >> 2);
    const int cbase = n0 + n_w + (lane & 3) * 2;
#pragma unroll
    for (int mb = 0; mb < 2; mb++) {
#pragma unroll
        for (int nb = 0; nb < 8; nb++) {
            float* p0 = g_xproj + (size_t)(rbase + mb * 16) * 512 + cbase + nb * 8;
            float* p1 = p0 + 8 * 512;
            *(float2*)p0 = make_float2(acc[mb][nb][0], acc[mb][nb][1]);
            *(float2*)p1 = make_float2(acc[mb][nb][2], acc[mb][nb][3]);
        }
    }
}

// ============================================================================
// Kernel 2: recurrent scan via mma.sync, register-resident W_h (R13 base).
// R14 delta: the 48-deep RAW chain on dacc is split into THREE independent
// accumulators (one per split term), summed after the loop — dependent-chain
// length 48 -> 16 HMMAs. rmb[8] register array replaced by in-loop mapa.
// ============================================================================
#define HC_BSTRIDE  2080            // byte stride between batch rows
#define HC_BUF      16640           // one h buffer (8 rows x 2080)
#define STG_OFF     (2 * HC_BUF)    // 33280
#define MBAR_OFF2   (STG_OFF + 2048)// 35328
#define SCAN_SMEM   (MBAR_OFF2 + 32)
#define TX_BYTES    16384u

__device__ __forceinline__ int rowoff(int b) {
    return b * HC_BSTRIDE;          // multiple of 8 for every row
}

__global__ void __cluster_dims__(8, 1, 1) __launch_bounds__(256, 1)
rnn_scan(const float* __restrict__ Wh, const float* __restrict__ bh,
         float* __restrict__ out) {
    extern __shared__ __align__(16) char sm[];
    char*  hc  = sm;                          // [2][HC_BUF] h cells
    float* stg = (float*)(sm + STG_OFF);      // [4][32] float4 staging

    const int tid   = threadIdx.x;
    const int lane  = tid & 31;
    const int w     = tid >> 5;
    const int j     = w >> 1;        // m-block 0..3
    const int kh    = w & 1;         // k-half
    const int rk    = blockIdx.x & 7;    // cluster rank -> dim slice
    const int g     = blockIdx.x >> 3;   // batch group
    const int row_l = lane >> 2;     // 0..7 (A-row low / B-n)
    const int qb    = lane & 3;

    const uint32_t smb     = (uint32_t)__cvta_generic_to_shared(sm);
    const uint32_t mb_u32  = smb + MBAR_OFF2;

    const int d_base = rk * 64 + j * 16;

    // ---- W_h fragments into registers (bf16 hi/lo split), one-time ----
    uint32_t whi[16][4], wlo[16][4];
    {
        const float* Wr0 = Wh + (size_t)(d_base + row_l) * 512 + kh * 256;
        const float* Wr1 = Wr0 + 8 * 512;
#pragma unroll
        for (int ks = 0; ks < 16; ks++) {
            const int k0 = ks * 16 + qb * 2;
            float2 q00 = *(const float2*)(Wr0 + k0);
            float2 q10 = *(const float2*)(Wr1 + k0);
            float2 q01 = *(const float2*)(Wr0 + k0 + 8);
            float2 q11 = *(const float2*)(Wr1 + k0 + 8);
            split2(q00.x, q00.y, whi[ks][0], wlo[ks][0]);
            split2(q10.x, q10.y, whi[ks][1], wlo[ks][1]);
            split2(q01.x, q01.y, whi[ks][2], wlo[ks][2]);
            split2(q11.x, q11.y, whi[ks][3], wlo[ks][3]);
        }
    }

    // ---- zero h buffer 0 (t=0 reads zeros) ----
    for (int i = tid; i < HC_BUF / 8; i += 256) ((u64*)hc)[i] = 0ull;
    if (tid == 0) {
        mbar_init(mb_u32 + 0, 1);
        mbar_init(mb_u32 + 8, 1);
    }
    __syncthreads();
    asm volatile("barrier.cluster.arrive.aligned;" ::: "memory");
    asm volatile("barrier.cluster.wait.aligned;"   ::: "memory");
    if (tid == 0) {
        mbar_expect_tx(mb_u32 + 0, TX_BYTES);
        mbar_expect_tx(mb_u32 + 8, TX_BYTES);
    }
    asm volatile("barrier.cluster.arrive.aligned;" ::: "memory");
    asm volatile("barrier.cluster.wait.aligned;"   ::: "memory");

    // ---- B-frag read base: batch row = row_l, k-pair = kh*128 + ks*8 + qb --
    const char* hbase = hc + rowoff(row_l) + (kh * 128 + qb) * 8;

    // ---- output/push mapping (even warps own final D after reduce) ----
    const int b0l   = qb * 2;                     // local batch pair
    const int bgl0  = g * 8 + b0l;
    const float bias0 = bh[d_base + row_l];
    const float bias1 = bh[d_base + row_l + 8];
    const float* xpb = g_xproj + ((size_t)bgl0 * 512 + d_base + row_l);

    // push destinations (even-r lanes of even warps): cell (b0l, dpA)
    const int dpA = rk * 32 + j * 8 + (row_l >> 1);
    uint32_t dst[8];
#pragma unroll
    for (int rr = 0; rr < 8; rr++) {
        asm("mapa.shared::cluster.u32 %0, %1, %2;"
            : "=r"(dst[rr])
            : "r"(smb + (uint32_t)(rowoff(b0l) + dpA * 8)), "r"(rr));
    }

    // prefetch xp(0)
    float xq0 = 0.f, xq1 = 0.f, xq2 = 0.f, xq3 = 0.f;
    if (!kh) {
        xq0 = __ldg(xpb);        xq1 = __ldg(xpb + 512);
        xq2 = __ldg(xpb + 8);    xq3 = __ldg(xpb + 520);
    }

    uint32_t ph0 = 0, ph1 = 0;

    for (int t = 0; t < T_STEPS; t++) {
        const int p = t & 1;

        if (t > 0) {
            const uint32_t mb = mb_u32 + (uint32_t)p * 8;
            mbar_wait_parity(mb, p ? ph1 : ph0);
            if (p) ph1 ^= 1; else ph0 ^= 1;
            if (tid == 0) mbar_expect_tx(mb, TX_BYTES);
        }

        // ---- mma over this warp's k-half: THREE independent chains ----
        float da[4] = {0.f, 0.f, 0.f, 0.f};   // whi * h_hi
        float db[4] = {0.f, 0.f, 0.f, 0.f};   // wlo * h_hi
        float dc[4] = {0.f, 0.f, 0.f, 0.f};   // whi * h_lo
        const char* hp = hbase + p * HC_BUF;
#pragma unroll
        for (int ks = 0; ks < 16; ks++) {
            const char* cp = hp + ks * 64;
            uint32_t bhv[2], blv[2];
            bhv[0] = *(const uint32_t*)(cp);
            blv[0] = *(const uint32_t*)(cp + 4);
            bhv[1] = *(const uint32_t*)(cp + 32);
            blv[1] = *(const uint32_t*)(cp + 36);
            mma16816(da, whi[ks], bhv);
            mma16816(db, wlo[ks], bhv);
            mma16816(dc, whi[ks], blv);
        }
        float dacc[4];
#pragma unroll
        for (int q = 0; q < 4; q++) dacc[q] = (da[q] + db[q]) + dc[q];

        // ---- k-half pair reduce via staging ----
        if (kh) {
            ((float4*)stg)[j * 32 + lane] =
                make_float4(dacc[0], dacc[1], dacc[2], dacc[3]);
        }
        __syncthreads();

        if (!kh) {
            float4 o = ((float4*)stg)[j * 32 + lane];
            const float z0 = dacc[0] + o.x + xq0 + bias0;  // (r,   b0)
            const float z1 = dacc[1] + o.y + xq1 + bias0;  // (r,   b1)
            const float z2 = dacc[2] + o.z + xq2 + bias1;  // (r+8, b0)
            const float z3 = dacc[3] + o.w + xq3 + bias1;
            const float h0 = 1.0f / (1.0f + __expf(-z0));
            const float h1 = 1.0f / (1.0f + __expf(-z1));
            const float h2 = 1.0f / (1.0f + __expf(-z2));
            const float h3 = 1.0f / (1.0f + __expf(-z3));

            if (t < T_STEPS - 1) {
                // partner (d+1) values live at lane+4 (row_l+1)
                const float n0 = __shfl_down_sync(0xffffffffu, h0, 4);
                const float n1 = __shfl_down_sync(0xffffffffu, h1, 4);
                const float n2 = __shfl_down_sync(0xffffffffu, h2, 4);
                const float n3 = __shfl_down_sync(0xffffffffu, h3, 4);
                if (!(row_l & 1)) {
                    const u64 cA0 = cellpack(h0, n0);   // (b0, dpA)
                    const u64 cA1 = cellpack(h1, n1);   // (b1, dpA)
                    const u64 cB0 = cellpack(h2, n2);   // (b0, dpA+4)
                    const u64 cB1 = cellpack(h3, n3);
                    const uint32_t qo = (uint32_t)((p ^ 1) * HC_BUF);
                    const uint32_t mloc = mb_u32 + (uint32_t)((p ^ 1) * 8);
#pragma unroll
                    for (int rr = 0; rr < 8; rr++) {
                        const uint32_t d0 = dst[rr] + qo;
                        uint32_t m0_;
                        asm("mapa.shared::cluster.u32 %0, %1, %2;"
                            : "=r"(m0_) : "r"(mloc), "r"(rr));
                        st_async_cluster_u64(d0, cA0, m0_);
                        st_async_cluster_u64(d0 + HC_BSTRIDE, cA1, m0_);
                        st_async_cluster_u64(d0 + 32, cB0, m0_);
                        st_async_cluster_u64(d0 + HC_BSTRIDE + 32, cB1, m0_);
                    }
                }
                // prefetch xp(t+1)
                const float* xn = xpb + (size_t)(t + 1) * BATCH * DIM;
                xq0 = __ldg(xn);      xq1 = __ldg(xn + 512);
                xq2 = __ldg(xn + 8);  xq3 = __ldg(xn + 520);
            } else {
                float* ob = out + (size_t)bgl0 * 512 + d_base + row_l;
                ob[0]       = h0;
                ob[512]     = h1;
                ob[8]       = h2;
                ob[520]     = h3;
            }
        }
    }

    // keep cluster alive for in-flight async stores
    asm volatile("barrier.cluster.arrive.aligned;" ::: "memory");
    asm volatile("barrier.cluster.wait.aligned;"   ::: "memory");
}

// ============================================================================
extern "C" void kernel_launch(void* const* d_in, const int* in_sizes, int n_in,
                              void* d_out, int out_size) {
    const float* X    = (const float*)d_in[0];  // [512,128,512]
    const float* W_in = (const float*)d_in[1];  // [512,512]
    const float* W_h  = (const float*)d_in[2];  // [512,512]
    const float* b_h  = (const float*)d_in[3];  // [512]
    float* out = (float*)d_out;                 // [128,512]

    (void)in_sizes; (void)n_in; (void)out_size;

    __nv_bfloat162 *xhi, *xlo, *whi, *wlo;
    cudaGetSymbolAddress((void**)&xhi, g_Xhi);
    cudaGetSymbolAddress((void**)&xlo, g_Xlo);
    cudaGetSymbolAddress((void**)&whi, g_Whi);
    cudaGetSymbolAddress((void**)&wlo, g_Wlo);

    // 0) split X and W_in into bf16 hi/lo
    split_kernel<<<(M_ROWS * DIM / 4 + 255) / 256, 256>>>(X, xhi, xlo,
                                                          M_ROWS * DIM / 4);
    split_kernel<<<(DIM * DIM / 4 + 255) / 256, 256>>>(W_in, whi, wlo,
                                                       DIM * DIM / 4);

    // 1) Xproj via mma.sync bf16 (3-split)
    cudaFuncSetAttribute(xproj_mma,
                         cudaFuncAttributeMaxDynamicSharedMemorySize,
                         GEMM2_SMEM);
    dim3 g1(DIM / 128, M_ROWS / 128);   // (4, 512)
    xproj_mma<<<g1, 256, GEMM2_SMEM>>>(
        (const __nv_bfloat16*)xhi, (const __nv_bfloat16*)xlo,
        (const __nv_bfloat16*)whi, (const __nv_bfloat16*)wlo);

    // 2) recurrent scan via mma.sync (register-resident W_h)
    rnn_scan<<<128, 256, SCAN_SMEM>>>(W_h, b_h, out);
}